// round 1
// baseline (speedup 1.0000x reference)
#include <cuda_runtime.h>

// Problem constants
#define BB 8
#define SS 1024
#define NX 1024
#define NH 16
#define HD 64          // head dim
// QKV row stride = 3*NX = 3072

// Scratch (device globals: allocation-free rule)
__device__ float g_qkv[(size_t)BB * SS * 3 * NX];   // (B, S, 3*NX)
__device__ float g_attn[(size_t)BB * SS * NX];      // (B, S, NX) merged heads

// ---------------------------------------------------------------------------
// SGEMM: C(MxN) = A(MxK) @ B(KxN) + bias(N).  BM=BN=128, BK=8, 8x8 microtile,
// 256 threads, global->register prefetch to hide HBM latency.
// Requires M%128==0, N%128==0, K%8==0 (true for all our shapes).
// ---------------------------------------------------------------------------
__global__ __launch_bounds__(256) void sgemm_bias(
    const float* __restrict__ A, const float* __restrict__ B,
    const float* __restrict__ bias, float* __restrict__ C,
    int M, int N, int K)
{
    __shared__ float As[8][128];
    __shared__ float Bs[8][128];

    int tid = threadIdx.x;
    int tx = tid & 15;        // 0..15 (column groups of 8)
    int ty = tid >> 4;        // 0..15 (row groups of 8)
    int bm = blockIdx.y * 128;
    int bn = blockIdx.x * 128;

    int arow = tid >> 1;          // 0..127
    int acol = (tid & 1) * 4;     // 0 or 4
    int brow = tid >> 5;          // 0..7
    int bcol = (tid & 31) * 4;    // 0..124

    const float* Ap = A + (size_t)(bm + arow) * K + acol;
    const float* Bp = B + (size_t)brow * N + bn + bcol;

    float4 av = *(const float4*)Ap;
    float4 bv = *(const float4*)Bp;

    float acc[8][8] = {};
    const int nt = K >> 3;

    for (int t = 0; t < nt; ++t) {
        As[acol + 0][arow] = av.x;
        As[acol + 1][arow] = av.y;
        As[acol + 2][arow] = av.z;
        As[acol + 3][arow] = av.w;
        *(float4*)&Bs[brow][bcol] = bv;
        __syncthreads();

        if (t + 1 < nt) {
            av = *(const float4*)(Ap + (size_t)(t + 1) * 8);
            bv = *(const float4*)(Bp + (size_t)(t + 1) * 8 * N);
        }

        #pragma unroll
        for (int k = 0; k < 8; ++k) {
            float a[8], b[8];
            *(float4*)&a[0] = *(float4*)&As[k][ty * 8];
            *(float4*)&a[4] = *(float4*)&As[k][ty * 8 + 4];
            *(float4*)&b[0] = *(float4*)&Bs[k][tx * 8];
            *(float4*)&b[4] = *(float4*)&Bs[k][tx * 8 + 4];
            #pragma unroll
            for (int i = 0; i < 8; ++i)
                #pragma unroll
                for (int j = 0; j < 8; ++j)
                    acc[i][j] += a[i] * b[j];
        }
        __syncthreads();
    }

    #pragma unroll
    for (int i = 0; i < 8; ++i) {
        int row = bm + ty * 8 + i;
        #pragma unroll
        for (int j = 0; j < 8; j += 4) {
            int col = bn + tx * 8 + j;
            float4 o;
            o.x = acc[i][j + 0] + bias[col + 0];
            o.y = acc[i][j + 1] + bias[col + 1];
            o.z = acc[i][j + 2] + bias[col + 2];
            o.w = acc[i][j + 3] + bias[col + 3];
            *(float4*)&C[(size_t)row * N + col] = o;
        }
    }
}

// ---------------------------------------------------------------------------
// Flash attention (fp32, causal). One block = (128 queries, 1 head, 1 batch).
// K/V tiles of 64 keys. 256 threads: tx(0..15) over 4-wide key/d columns,
// ty(0..15) over 8-wide query rows. Smem layouts chosen for conflict-free
// float4 LDS in both GEMMs.
// qkv layout: (B, S, 3*NX) with q at col h*64, k at NX+h*64, v at 2*NX+h*64.
// out layout: (B, S, NX) merged heads.
// ---------------------------------------------------------------------------
#define FLASH_SMEM_FLOATS (64*128 + 64*64 + 64*64 + 128*65)
#define FLASH_SMEM_BYTES  (FLASH_SMEM_FLOATS * 4)

__global__ __launch_bounds__(256) void flash_attn(
    const float* __restrict__ qkv, float* __restrict__ out)
{
    extern __shared__ float sm[];
    float* Qst = sm;                  // [d][q]  64 x 128  (d-major, transposed)
    float* Kst = Qst + 64 * 128;      // [d][k]  64 x 64   (d-major, transposed)
    float* Vs  = Kst + 64 * 64;       // [k][d]  64 x 64
    float* Ps  = Vs  + 64 * 64;       // [q][k]  128 x 65  (padded)

    int tid = threadIdx.x;
    int tx = tid & 15;
    int ty = tid >> 4;
    int qt = blockIdx.x;   // query tile (0..7)
    int h  = blockIdx.y;
    int b  = blockIdx.z;
    int q0 = qt * 128;

    const float* base = qkv + (size_t)b * SS * (3 * NX);
    const float* qb = base + (size_t)q0 * (3 * NX) + h * HD;
    const float* kb = base + NX + h * HD;
    const float* vb = base + 2 * NX + h * HD;

    // --- load Q tile transposed: Qst[d][q] ---
    {
        int q  = tid & 127;
        int d0 = (tid >> 7) * 32;
        const float* src = qb + (size_t)q * (3 * NX) + d0;
        #pragma unroll
        for (int i = 0; i < 8; ++i) {
            float4 v = *(const float4*)(src + i * 4);
            int d = d0 + i * 4;
            Qst[(d + 0) * 128 + q] = v.x;
            Qst[(d + 1) * 128 + q] = v.y;
            Qst[(d + 2) * 128 + q] = v.z;
            Qst[(d + 3) * 128 + q] = v.w;
        }
    }

    float acc[8][4] = {};
    float mprev[8], lsum[8];
    #pragma unroll
    for (int i = 0; i < 8; ++i) { mprev[i] = -1e30f; lsum[i] = 0.0f; }

    const int nkt = 2 * qt + 2;   // causal: k-tiles with k0 <= q0+127

    for (int kt = 0; kt < nkt; ++kt) {
        __syncthreads();   // previous iter's O-GEMM done reading Vs/Ps; Qst visible
        // --- load K tile transposed + V tile direct ---
        {
            int k  = tid & 63;
            int d0 = (tid >> 6) * 16;
            const float* ksrc = kb + (size_t)(kt * 64 + k) * (3 * NX) + d0;
            #pragma unroll
            for (int i = 0; i < 4; ++i) {
                float4 v = *(const float4*)(ksrc + i * 4);
                int d = d0 + i * 4;
                Kst[(d + 0) * 64 + k] = v.x;
                Kst[(d + 1) * 64 + k] = v.y;
                Kst[(d + 2) * 64 + k] = v.z;
                Kst[(d + 3) * 64 + k] = v.w;
            }
            const float* vsrc = vb + (size_t)(kt * 64 + k) * (3 * NX) + d0;
            #pragma unroll
            for (int i = 0; i < 4; ++i)
                *(float4*)&Vs[k * 64 + d0 + i * 4] = *(const float4*)(vsrc + i * 4);
        }
        __syncthreads();

        // --- scores: S(128x64) = Q @ K^T ---
        float s[8][4] = {};
        #pragma unroll 8
        for (int d = 0; d < 64; ++d) {
            float a[8], bk[4];
            *(float4*)&a[0]  = *(float4*)&Qst[d * 128 + ty * 8];
            *(float4*)&a[4]  = *(float4*)&Qst[d * 128 + ty * 8 + 4];
            *(float4*)&bk[0] = *(float4*)&Kst[d * 64 + tx * 4];
            #pragma unroll
            for (int i = 0; i < 8; ++i)
                #pragma unroll
                for (int j = 0; j < 4; ++j)
                    s[i][j] += a[i] * bk[j];
        }

        // --- scale + causal mask (matches reference: masked = exactly -1e10) ---
        bool domask = (kt >= 2 * qt);
        #pragma unroll
        for (int i = 0; i < 8; ++i) {
            int qg = q0 + ty * 8 + i;
            #pragma unroll
            for (int j = 0; j < 4; ++j) {
                s[i][j] *= 0.125f;   // 1/sqrt(64)
                if (domask) {
                    int kg = kt * 64 + tx * 4 + j;
                    if (kg > qg) s[i][j] = -1e10f;
                }
            }
        }

        // --- online softmax (row reductions across the 16 tx lanes) ---
        #pragma unroll
        for (int i = 0; i < 8; ++i) {
            float mx = fmaxf(fmaxf(s[i][0], s[i][1]), fmaxf(s[i][2], s[i][3]));
            #pragma unroll
            for (int off = 1; off < 16; off <<= 1)
                mx = fmaxf(mx, __shfl_xor_sync(0xffffffffu, mx, off));
            float mnew  = fmaxf(mprev[i], mx);
            float alpha = __expf(mprev[i] - mnew);
            float rs = 0.0f;
            #pragma unroll
            for (int j = 0; j < 4; ++j) {
                s[i][j] = __expf(s[i][j] - mnew);
                rs += s[i][j];
            }
            #pragma unroll
            for (int off = 1; off < 16; off <<= 1)
                rs += __shfl_xor_sync(0xffffffffu, rs, off);
            lsum[i]  = lsum[i] * alpha + rs;
            mprev[i] = mnew;
            #pragma unroll
            for (int j = 0; j < 4; ++j) acc[i][j] *= alpha;
        }

        // --- write P to shared ---
        #pragma unroll
        for (int i = 0; i < 8; ++i)
            #pragma unroll
            for (int j = 0; j < 4; ++j)
                Ps[(ty * 8 + i) * 65 + tx * 4 + j] = s[i][j];
        __syncthreads();

        // --- O += P @ V ---
        #pragma unroll 4
        for (int kk = 0; kk < 64; ++kk) {
            float bv[4];
            *(float4*)&bv[0] = *(float4*)&Vs[kk * 64 + tx * 4];
            #pragma unroll
            for (int i = 0; i < 8; ++i) {
                float ap = Ps[(ty * 8 + i) * 65 + kk];
                #pragma unroll
                for (int j = 0; j < 4; ++j)
                    acc[i][j] += ap * bv[j];
            }
        }
    }

    // --- epilogue: normalize and store merged-head output ---
    float* ob = out + ((size_t)b * SS + q0) * NX + h * HD;
    #pragma unroll
    for (int i = 0; i < 8; ++i) {
        float inv = 1.0f / lsum[i];
        float4 o;
        o.x = acc[i][0] * inv;
        o.y = acc[i][1] * inv;
        o.z = acc[i][2] * inv;
        o.w = acc[i][3] * inv;
        *(float4*)&ob[(size_t)(ty * 8 + i) * NX + tx * 4] = o;
    }
}

// ---------------------------------------------------------------------------
extern "C" void kernel_launch(void* const* d_in, const int* in_sizes, int n_in,
                              void* d_out, int out_size)
{
    const float* x      = (const float*)d_in[0];
    const float* w_attn = (const float*)d_in[1];
    const float* b_attn = (const float*)d_in[2];
    const float* w_proj = (const float*)d_in[3];
    const float* b_proj = (const float*)d_in[4];
    float* out = (float*)d_out;

    float *qkv, *attn;
    cudaGetSymbolAddress((void**)&qkv,  g_qkv);
    cudaGetSymbolAddress((void**)&attn, g_attn);

    // 1) QKV = x @ w_attn + b_attn   (8192x1024 @ 1024x3072)
    {
        dim3 grid(3 * NX / 128, BB * SS / 128);   // 24 x 64
        sgemm_bias<<<grid, 256>>>(x, w_attn, b_attn, qkv, BB * SS, 3 * NX, NX);
    }

    // 2) flash attention per (qtile, head, batch)
    {
        cudaFuncSetAttribute(flash_attn,
                             cudaFuncAttributeMaxDynamicSharedMemorySize,
                             FLASH_SMEM_BYTES);
        dim3 grid(SS / 128, NH, BB);              // 8 x 16 x 8
        flash_attn<<<grid, 256, FLASH_SMEM_BYTES>>>(qkv, attn);
    }

    // 3) out = attn @ w_proj + b_proj   (8192x1024 @ 1024x1024)
    {
        dim3 grid(NX / 128, BB * SS / 128);       // 8 x 64
        sgemm_bias<<<grid, 256>>>(attn, w_proj, b_proj, out, BB * SS, NX, NX);
    }
}

// round 3
// speedup vs baseline: 1.6869x; 1.6869x over previous
#include <cuda_runtime.h>
#include <cuda_bf16.h>
#include <cstdint>

// Problem constants
#define BB 8
#define SS 1024
#define NX 1024
#define NH 16
#define HD 64

// ---------------------------------------------------------------------------
// Scratch (device globals; allocation-free rule)
// ---------------------------------------------------------------------------
__device__ float g_qkv[(size_t)BB * SS * 3 * NX];                 // (B,S,3NX) fp32
__device__ __nv_bfloat16 g_xhi[(size_t)BB * SS * NX];             // x split
__device__ __nv_bfloat16 g_xlo[(size_t)BB * SS * NX];
__device__ __nv_bfloat16 g_wahi[(size_t)3 * NX * NX];             // w_attn^T [3NX][NX]
__device__ __nv_bfloat16 g_walo[(size_t)3 * NX * NX];
__device__ __nv_bfloat16 g_wphi[(size_t)NX * NX];                 // w_proj^T [NX][NX]
__device__ __nv_bfloat16 g_wplo[(size_t)NX * NX];
__device__ __nv_bfloat16 g_ahi[(size_t)BB * SS * NX];             // attn out split
__device__ __nv_bfloat16 g_alo[(size_t)BB * SS * NX];

__device__ __forceinline__ uint32_t smem_to_u32(const void* p) {
    uint32_t a;
    asm("{ .reg .u64 t; cvta.to.shared.u64 t, %1; cvt.u32.u64 %0, t; }"
        : "=r"(a) : "l"(p));
    return a;
}

// ---------------------------------------------------------------------------
// Prepass: fp32 -> (hi,lo) bf16 split, same layout
// ---------------------------------------------------------------------------
__global__ void split_bf16(const float4* __restrict__ in,
                           __nv_bfloat16* __restrict__ hi,
                           __nv_bfloat16* __restrict__ lo, int n4)
{
    int i = blockIdx.x * blockDim.x + threadIdx.x;
    if (i >= n4) return;
    float4 v = in[i];
    __nv_bfloat16 h0 = __float2bfloat16(v.x);
    __nv_bfloat16 h1 = __float2bfloat16(v.y);
    __nv_bfloat16 h2 = __float2bfloat16(v.z);
    __nv_bfloat16 h3 = __float2bfloat16(v.w);
    __nv_bfloat16 l0 = __float2bfloat16(v.x - __bfloat162float(h0));
    __nv_bfloat16 l1 = __float2bfloat16(v.y - __bfloat162float(h1));
    __nv_bfloat16 l2 = __float2bfloat16(v.z - __bfloat162float(h2));
    __nv_bfloat16 l3 = __float2bfloat16(v.w - __bfloat162float(h3));
    __nv_bfloat162 hp0(h0, h1), hp1(h2, h3), lp0(l0, l1), lp1(l2, l3);
    uint2 hw, lw;
    hw.x = *(uint32_t*)&hp0; hw.y = *(uint32_t*)&hp1;
    lw.x = *(uint32_t*)&lp0; lw.y = *(uint32_t*)&lp1;
    *(uint2*)(hi + (size_t)i * 4) = hw;
    *(uint2*)(lo + (size_t)i * 4) = lw;
}

// Prepass: transpose K x C fp32 -> [C][K] (hi,lo) bf16 split
__global__ void transpose_split(const float* __restrict__ in,
                                __nv_bfloat16* __restrict__ hiT,
                                __nv_bfloat16* __restrict__ loT,
                                int Kdim, int Cdim)
{
    __shared__ float tile[32][33];
    int bx = blockIdx.x * 32;   // col (n) base
    int by = blockIdx.y * 32;   // row (k) base
    int x = threadIdx.x, y = threadIdx.y;  // 32 x 8
    #pragma unroll
    for (int j = 0; j < 4; ++j)
        tile[y + j * 8][x] = in[(size_t)(by + y + j * 8) * Cdim + bx + x];
    __syncthreads();
    #pragma unroll
    for (int j = 0; j < 4; ++j) {
        float v = tile[x][y + j * 8];
        __nv_bfloat16 h = __float2bfloat16(v);
        __nv_bfloat16 l = __float2bfloat16(v - __bfloat162float(h));
        size_t o = (size_t)(bx + y + j * 8) * Kdim + by + x;
        hiT[o] = h;
        loT[o] = l;
    }
}

// ---------------------------------------------------------------------------
// mma.sync GEMM: C(MxN) = A(MxK) @ BT(NxK)^T + bias, split-bf16 compensated.
// Block = 128x128 tile, BK=32, 8 warps (2x4), warp tile 64x32, double buffer.
// Smem row stride 40 bf16 (80B) -> conflict-free ldmatrix.
// ---------------------------------------------------------------------------
#define PLANE_B   10240          // 128 rows * 40 bf16 * 2B
#define PLANE_E   5120           // elements
#define STAGE_B   40960          // 4 planes
#define GEMM_SMEM (2 * STAGE_B)

__device__ __forceinline__ void mma16816(float* d, const uint32_t* a,
                                         const uint32_t* b) {
    asm volatile(
        "mma.sync.aligned.m16n8k16.row.col.f32.bf16.bf16.f32 "
        "{%0,%1,%2,%3}, {%4,%5,%6,%7}, {%8,%9}, {%0,%1,%2,%3};"
        : "+f"(d[0]), "+f"(d[1]), "+f"(d[2]), "+f"(d[3])
        : "r"(a[0]), "r"(a[1]), "r"(a[2]), "r"(a[3]), "r"(b[0]), "r"(b[1]));
}

__device__ __forceinline__ void ldsm_x4(uint32_t* r, uint32_t addr) {
    asm volatile("ldmatrix.sync.aligned.m8n8.x4.shared.b16 {%0,%1,%2,%3}, [%4];"
                 : "=r"(r[0]), "=r"(r[1]), "=r"(r[2]), "=r"(r[3]) : "r"(addr));
}

__device__ __forceinline__ void ldsm_x2(uint32_t* r, uint32_t addr) {
    asm volatile("ldmatrix.sync.aligned.m8n8.x2.shared.b16 {%0,%1}, [%2];"
                 : "=r"(r[0]), "=r"(r[1]) : "r"(addr));
}

__global__ __launch_bounds__(256, 1) void mma_gemm(
    const __nv_bfloat16* __restrict__ Ahi, const __nv_bfloat16* __restrict__ Alo,
    const __nv_bfloat16* __restrict__ BThi, const __nv_bfloat16* __restrict__ BTlo,
    const float* __restrict__ bias, float* __restrict__ C,
    int N, int K)
{
    extern __shared__ __align__(16) char sm[];
    const uint32_t smb = smem_to_u32(sm);

    const int tid  = threadIdx.x;
    const int warp = tid >> 5;
    const int lane = tid & 31;
    const int wm   = warp >> 2;        // 0..1
    const int wn   = warp & 3;         // 0..3
    const int bm   = blockIdx.y * 128;
    const int bn   = blockIdx.x * 128;

    // gmem staging coordinates: rows r0, r0+64 ; col chunk of 8
    const int r0 = tid >> 2;
    const int c8 = (tid & 3) * 8;

    // ldmatrix lane coordinates
    const int arow = (lane & 15);             // A: row within 16
    const int ak8  = ((lane >> 4) & 1) << 3;  // A: k offset 0/8
    const int brow = (lane & 7);              // B: row within 8
    const int bk8  = ((lane >> 3) & 1) << 3;  // B: k offset 0/8 (lanes 0..15)

    float acc[4][4][4];
    #pragma unroll
    for (int i = 0; i < 4; ++i)
        #pragma unroll
        for (int j = 0; j < 4; ++j)
            #pragma unroll
            for (int k = 0; k < 4; ++k) acc[i][j][k] = 0.0f;

    uint4 v[8];
    auto gload = [&](int t) {
        size_t ka = (size_t)t * 32 + c8;
        v[0] = *(const uint4*)(Ahi  + (size_t)(bm + r0)      * K + ka);
        v[1] = *(const uint4*)(Ahi  + (size_t)(bm + r0 + 64) * K + ka);
        v[2] = *(const uint4*)(Alo  + (size_t)(bm + r0)      * K + ka);
        v[3] = *(const uint4*)(Alo  + (size_t)(bm + r0 + 64) * K + ka);
        v[4] = *(const uint4*)(BThi + (size_t)(bn + r0)      * K + ka);
        v[5] = *(const uint4*)(BThi + (size_t)(bn + r0 + 64) * K + ka);
        v[6] = *(const uint4*)(BTlo + (size_t)(bn + r0)      * K + ka);
        v[7] = *(const uint4*)(BTlo + (size_t)(bn + r0 + 64) * K + ka);
    };
    auto sstore = [&](int s) {
        __nv_bfloat16* st = (__nv_bfloat16*)(sm + s * STAGE_B);
        #pragma unroll
        for (int p = 0; p < 4; ++p) {
            *(uint4*)(st + p * PLANE_E + (size_t)r0 * 40 + c8)        = v[2 * p];
            *(uint4*)(st + p * PLANE_E + (size_t)(r0 + 64) * 40 + c8) = v[2 * p + 1];
        }
    };

    const int nstage = K >> 5;   // 32

    gload(0);
    sstore(0);
    __syncthreads();

    for (int t = 0; t < nstage; ++t) {
        const int s = t & 1;
        if (t + 1 < nstage) gload(t + 1);

        const uint32_t pAh = smb + s * STAGE_B;
        const uint32_t pAl = pAh + PLANE_B;
        const uint32_t pBh = pAh + 2 * PLANE_B;
        const uint32_t pBl = pAh + 3 * PLANE_B;

        #pragma unroll
        for (int kc = 0; kc < 32; kc += 16) {
            // B fragments (hi & lo) for all 4 n-tiles
            uint32_t bh[4][2], bl[4][2];
            #pragma unroll
            for (int ntl = 0; ntl < 4; ++ntl) {
                uint32_t boff = (uint32_t)(wn * 32 + ntl * 8 + brow) * 80
                              + (uint32_t)(kc + bk8) * 2;
                ldsm_x2(bh[ntl], pBh + boff);
                ldsm_x2(bl[ntl], pBl + boff);
            }
            #pragma unroll
            for (int mt = 0; mt < 4; ++mt) {
                uint32_t aoff = (uint32_t)(wm * 64 + mt * 16 + arow) * 80
                              + (uint32_t)(kc + ak8) * 2;
                uint32_t ah[4], al[4];
                ldsm_x4(ah, pAh + aoff);
                ldsm_x4(al, pAl + aoff);
                #pragma unroll
                for (int ntl = 0; ntl < 4; ++ntl) {
                    mma16816(acc[mt][ntl], ah, bh[ntl]);   // Ah*Bh
                    mma16816(acc[mt][ntl], ah, bl[ntl]);   // Ah*Bl
                    mma16816(acc[mt][ntl], al, bh[ntl]);   // Al*Bh
                }
            }
        }

        if (t + 1 < nstage) sstore(s ^ 1);
        __syncthreads();
    }

    // epilogue
    const int g   = lane >> 2;
    const int tig = lane & 3;
    #pragma unroll
    for (int ntl = 0; ntl < 4; ++ntl) {
        int col = bn + wn * 32 + ntl * 8 + tig * 2;
        float b0 = __ldg(bias + col);
        float b1 = __ldg(bias + col + 1);
        #pragma unroll
        for (int mt = 0; mt < 4; ++mt) {
            int row = bm + wm * 64 + mt * 16 + g;
            float2 o0, o1;
            o0.x = acc[mt][ntl][0] + b0;
            o0.y = acc[mt][ntl][1] + b1;
            o1.x = acc[mt][ntl][2] + b0;
            o1.y = acc[mt][ntl][3] + b1;
            *(float2*)&C[(size_t)row * N + col]       = o0;
            *(float2*)&C[(size_t)(row + 8) * N + col] = o1;
        }
    }
}

// ---------------------------------------------------------------------------
// Flash attention (fp32, causal) — epilogue writes split bf16 merged heads.
// ---------------------------------------------------------------------------
#define FLASH_SMEM_FLOATS (64*128 + 64*64 + 64*64 + 128*65)
#define FLASH_SMEM_BYTES  (FLASH_SMEM_FLOATS * 4)

__global__ __launch_bounds__(256) void flash_attn(
    const float* __restrict__ qkv,
    __nv_bfloat16* __restrict__ outh, __nv_bfloat16* __restrict__ outl)
{
    extern __shared__ float smf[];
    float* Qst = smf;
    float* Kst = Qst + 64 * 128;
    float* Vs  = Kst + 64 * 64;
    float* Ps  = Vs  + 64 * 64;

    int tid = threadIdx.x;
    int tx = tid & 15;
    int ty = tid >> 4;
    int qt = blockIdx.x;
    int h  = blockIdx.y;
    int b  = blockIdx.z;
    int q0 = qt * 128;

    const float* base = qkv + (size_t)b * SS * (3 * NX);
    const float* qb = base + (size_t)q0 * (3 * NX) + h * HD;
    const float* kb = base + NX + h * HD;
    const float* vb = base + 2 * NX + h * HD;

    {
        int q  = tid & 127;
        int d0 = (tid >> 7) * 32;
        const float* src = qb + (size_t)q * (3 * NX) + d0;
        #pragma unroll
        for (int i = 0; i < 8; ++i) {
            float4 v = *(const float4*)(src + i * 4);
            int d = d0 + i * 4;
            Qst[(d + 0) * 128 + q] = v.x;
            Qst[(d + 1) * 128 + q] = v.y;
            Qst[(d + 2) * 128 + q] = v.z;
            Qst[(d + 3) * 128 + q] = v.w;
        }
    }

    float acc[8][4] = {};
    float mprev[8], lsum[8];
    #pragma unroll
    for (int i = 0; i < 8; ++i) { mprev[i] = -1e30f; lsum[i] = 0.0f; }

    const int nkt = 2 * qt + 2;

    for (int kt = 0; kt < nkt; ++kt) {
        __syncthreads();
        {
            int k  = tid & 63;
            int d0 = (tid >> 6) * 16;
            const float* ksrc = kb + (size_t)(kt * 64 + k) * (3 * NX) + d0;
            #pragma unroll
            for (int i = 0; i < 4; ++i) {
                float4 v = *(const float4*)(ksrc + i * 4);
                int d = d0 + i * 4;
                Kst[(d + 0) * 64 + k] = v.x;
                Kst[(d + 1) * 64 + k] = v.y;
                Kst[(d + 2) * 64 + k] = v.z;
                Kst[(d + 3) * 64 + k] = v.w;
            }
            const float* vsrc = vb + (size_t)(kt * 64 + k) * (3 * NX) + d0;
            #pragma unroll
            for (int i = 0; i < 4; ++i)
                *(float4*)&Vs[k * 64 + d0 + i * 4] = *(const float4*)(vsrc + i * 4);
        }
        __syncthreads();

        float s[8][4] = {};
        #pragma unroll 8
        for (int d = 0; d < 64; ++d) {
            float a[8], bk[4];
            *(float4*)&a[0]  = *(float4*)&Qst[d * 128 + ty * 8];
            *(float4*)&a[4]  = *(float4*)&Qst[d * 128 + ty * 8 + 4];
            *(float4*)&bk[0] = *(float4*)&Kst[d * 64 + tx * 4];
            #pragma unroll
            for (int i = 0; i < 8; ++i)
                #pragma unroll
                for (int j = 0; j < 4; ++j)
                    s[i][j] += a[i] * bk[j];
        }

        bool domask = (kt >= 2 * qt);
        #pragma unroll
        for (int i = 0; i < 8; ++i) {
            int qg = q0 + ty * 8 + i;
            #pragma unroll
            for (int j = 0; j < 4; ++j) {
                s[i][j] *= 0.125f;
                if (domask) {
                    int kg = kt * 64 + tx * 4 + j;
                    if (kg > qg) s[i][j] = -1e10f;
                }
            }
        }

        #pragma unroll
        for (int i = 0; i < 8; ++i) {
            float mx = fmaxf(fmaxf(s[i][0], s[i][1]), fmaxf(s[i][2], s[i][3]));
            #pragma unroll
            for (int off = 1; off < 16; off <<= 1)
                mx = fmaxf(mx, __shfl_xor_sync(0xffffffffu, mx, off));
            float mnew  = fmaxf(mprev[i], mx);
            float alpha = __expf(mprev[i] - mnew);
            float rs = 0.0f;
            #pragma unroll
            for (int j = 0; j < 4; ++j) {
                s[i][j] = __expf(s[i][j] - mnew);
                rs += s[i][j];
            }
            #pragma unroll
            for (int off = 1; off < 16; off <<= 1)
                rs += __shfl_xor_sync(0xffffffffu, rs, off);
            lsum[i]  = lsum[i] * alpha + rs;
            mprev[i] = mnew;
            #pragma unroll
            for (int j = 0; j < 4; ++j) acc[i][j] *= alpha;
        }

        #pragma unroll
        for (int i = 0; i < 8; ++i)
            #pragma unroll
            for (int j = 0; j < 4; ++j)
                Ps[(ty * 8 + i) * 65 + tx * 4 + j] = s[i][j];
        __syncthreads();

        #pragma unroll 4
        for (int kk = 0; kk < 64; ++kk) {
            float bv[4];
            *(float4*)&bv[0] = *(float4*)&Vs[kk * 64 + tx * 4];
            #pragma unroll
            for (int i = 0; i < 8; ++i) {
                float ap = Ps[(ty * 8 + i) * 65 + kk];
                #pragma unroll
                for (int j = 0; j < 4; ++j)
                    acc[i][j] += ap * bv[j];
            }
        }
    }

    size_t ob = ((size_t)b * SS + q0) * NX + h * HD;
    #pragma unroll
    for (int i = 0; i < 8; ++i) {
        float inv = 1.0f / lsum[i];
        float v0 = acc[i][0] * inv, v1 = acc[i][1] * inv;
        float v2 = acc[i][2] * inv, v3 = acc[i][3] * inv;
        __nv_bfloat16 h0 = __float2bfloat16(v0), h1 = __float2bfloat16(v1);
        __nv_bfloat16 h2 = __float2bfloat16(v2), h3 = __float2bfloat16(v3);
        __nv_bfloat16 l0 = __float2bfloat16(v0 - __bfloat162float(h0));
        __nv_bfloat16 l1 = __float2bfloat16(v1 - __bfloat162float(h1));
        __nv_bfloat16 l2 = __float2bfloat16(v2 - __bfloat162float(h2));
        __nv_bfloat16 l3 = __float2bfloat16(v3 - __bfloat162float(h3));
        __nv_bfloat162 hp0(h0, h1), hp1(h2, h3), lp0(l0, l1), lp1(l2, l3);
        uint2 hw, lw;
        hw.x = *(uint32_t*)&hp0; hw.y = *(uint32_t*)&hp1;
        lw.x = *(uint32_t*)&lp0; lw.y = *(uint32_t*)&lp1;
        size_t off = ob + (size_t)(ty * 8 + i) * NX + tx * 4;
        *(uint2*)(outh + off) = hw;
        *(uint2*)(outl + off) = lw;
    }
}

// ---------------------------------------------------------------------------
extern "C" void kernel_launch(void* const* d_in, const int* in_sizes, int n_in,
                              void* d_out, int out_size)
{
    const float* x      = (const float*)d_in[0];
    const float* w_attn = (const float*)d_in[1];
    const float* b_attn = (const float*)d_in[2];
    const float* w_proj = (const float*)d_in[3];
    const float* b_proj = (const float*)d_in[4];
    float* out = (float*)d_out;

    float* qkv;
    __nv_bfloat16 *xhi, *xlo, *wahi, *walo, *wphi, *wplo, *ahi, *alo;
    cudaGetSymbolAddress((void**)&qkv,  g_qkv);
    cudaGetSymbolAddress((void**)&xhi,  g_xhi);
    cudaGetSymbolAddress((void**)&xlo,  g_xlo);
    cudaGetSymbolAddress((void**)&wahi, g_wahi);
    cudaGetSymbolAddress((void**)&walo, g_walo);
    cudaGetSymbolAddress((void**)&wphi, g_wphi);
    cudaGetSymbolAddress((void**)&wplo, g_wplo);
    cudaGetSymbolAddress((void**)&ahi,  g_ahi);
    cudaGetSymbolAddress((void**)&alo,  g_alo);

    // prepass: split x; transpose+split weights
    {
        int n4 = BB * SS * NX / 4;
        split_bf16<<<(n4 + 255) / 256, 256>>>((const float4*)x, xhi, xlo, n4);
        transpose_split<<<dim3(3 * NX / 32, NX / 32), dim3(32, 8)>>>(
            w_attn, wahi, walo, NX, 3 * NX);
        transpose_split<<<dim3(NX / 32, NX / 32), dim3(32, 8)>>>(
            w_proj, wphi, wplo, NX, NX);
    }

    cudaFuncSetAttribute(mma_gemm, cudaFuncAttributeMaxDynamicSharedMemorySize,
                         GEMM_SMEM);

    // 1) QKV = x @ w_attn + b_attn
    {
        dim3 grid(3 * NX / 128, BB * SS / 128);    // 24 x 64
        mma_gemm<<<grid, 256, GEMM_SMEM>>>(xhi, xlo, wahi, walo, b_attn, qkv,
                                           3 * NX, NX);
    }

    // 2) flash attention -> split-bf16 merged heads
    {
        cudaFuncSetAttribute(flash_attn, cudaFuncAttributeMaxDynamicSharedMemorySize,
                             FLASH_SMEM_BYTES);
        dim3 grid(SS / 128, NH, BB);
        flash_attn<<<grid, 256, FLASH_SMEM_BYTES>>>(qkv, ahi, alo);
    }

    // 3) out = attn @ w_proj + b_proj
    {
        dim3 grid(NX / 128, BB * SS / 128);        // 8 x 64
        mma_gemm<<<grid, 256, GEMM_SMEM>>>(ahi, alo, wphi, wplo, b_proj, out,
                                           NX, NX);
    }
}

// round 4
// speedup vs baseline: 2.6971x; 1.5988x over previous
#include <cuda_runtime.h>
#include <cuda_bf16.h>
#include <cuda_fp16.h>
#include <cstdint>

// Problem constants
#define BB 8
#define SS 1024
#define NX 1024
#define NH 16
#define HD 64

// log2(e) * (1/sqrt(64)) folded into Q
#define CSC 0.18033688011112042592f

// ---------------------------------------------------------------------------
// Scratch (device globals; allocation-free rule)
// ---------------------------------------------------------------------------
__device__ __nv_bfloat16 g_xhi[(size_t)BB * SS * NX];
__device__ __nv_bfloat16 g_xlo[(size_t)BB * SS * NX];
__device__ __nv_bfloat16 g_wahi[(size_t)3 * NX * NX];   // w_attn^T [3NX][NX]
__device__ __nv_bfloat16 g_walo[(size_t)3 * NX * NX];
__device__ __nv_bfloat16 g_wphi[(size_t)NX * NX];       // w_proj^T [NX][NX]
__device__ __nv_bfloat16 g_wplo[(size_t)NX * NX];
// QKV projections, converted for flash
__device__ __nv_bfloat16 g_qh[(size_t)BB * SS * NX];    // Q scaled by CSC, hi
__device__ __nv_bfloat16 g_ql[(size_t)BB * SS * NX];
__device__ __nv_bfloat16 g_kh[(size_t)BB * SS * NX];
__device__ __nv_bfloat16 g_kl[(size_t)BB * SS * NX];
__device__ __half        g_vh[(size_t)BB * SS * NX];
// attention output, split for proj GEMM
__device__ __nv_bfloat16 g_ahi[(size_t)BB * SS * NX];
__device__ __nv_bfloat16 g_alo[(size_t)BB * SS * NX];

__device__ __forceinline__ uint32_t smem_to_u32(const void* p) {
    uint32_t a;
    asm("{ .reg .u64 t; cvta.to.shared.u64 t, %1; cvt.u32.u64 %0, t; }"
        : "=r"(a) : "l"(p));
    return a;
}

// ---------------------------------------------------------------------------
// MMA / ldmatrix helpers
// ---------------------------------------------------------------------------
__device__ __forceinline__ void mma_bf16(float* d, const uint32_t* a,
                                         const uint32_t* b) {
    asm volatile(
        "mma.sync.aligned.m16n8k16.row.col.f32.bf16.bf16.f32 "
        "{%0,%1,%2,%3}, {%4,%5,%6,%7}, {%8,%9}, {%0,%1,%2,%3};"
        : "+f"(d[0]), "+f"(d[1]), "+f"(d[2]), "+f"(d[3])
        : "r"(a[0]), "r"(a[1]), "r"(a[2]), "r"(a[3]), "r"(b[0]), "r"(b[1]));
}

__device__ __forceinline__ void mma_f16(float* d, const uint32_t* a,
                                        const uint32_t* b) {
    asm volatile(
        "mma.sync.aligned.m16n8k16.row.col.f32.f16.f16.f32 "
        "{%0,%1,%2,%3}, {%4,%5,%6,%7}, {%8,%9}, {%0,%1,%2,%3};"
        : "+f"(d[0]), "+f"(d[1]), "+f"(d[2]), "+f"(d[3])
        : "r"(a[0]), "r"(a[1]), "r"(a[2]), "r"(a[3]), "r"(b[0]), "r"(b[1]));
}

__device__ __forceinline__ void ldsm_x4(uint32_t* r, uint32_t addr) {
    asm volatile("ldmatrix.sync.aligned.m8n8.x4.shared.b16 {%0,%1,%2,%3}, [%4];"
                 : "=r"(r[0]), "=r"(r[1]), "=r"(r[2]), "=r"(r[3]) : "r"(addr));
}

__device__ __forceinline__ void ldsm_x4_t(uint32_t* r, uint32_t addr) {
    asm volatile("ldmatrix.sync.aligned.m8n8.x4.trans.shared.b16 {%0,%1,%2,%3}, [%4];"
                 : "=r"(r[0]), "=r"(r[1]), "=r"(r[2]), "=r"(r[3]) : "r"(addr));
}

__device__ __forceinline__ void ldsm_x2(uint32_t* r, uint32_t addr) {
    asm volatile("ldmatrix.sync.aligned.m8n8.x2.shared.b16 {%0,%1}, [%2];"
                 : "=r"(r[0]), "=r"(r[1]) : "r"(addr));
}

__device__ __forceinline__ float ex2f(float x) {
    float r;
    asm("ex2.approx.ftz.f32 %0, %1;" : "=f"(r) : "f"(x));
    return r;
}

// pack half2(hi, lo) then ex2 both
__device__ __forceinline__ uint32_t ex2_pack(float hi, float lo) {
    uint32_t t, r;
    asm("cvt.rn.f16x2.f32 %0, %1, %2;" : "=r"(t) : "f"(hi), "f"(lo));
    asm("ex2.approx.f16x2 %0, %1;" : "=r"(r) : "r"(t));
    return r;
}

__device__ __forceinline__ void st_split(__nv_bfloat16* hp, __nv_bfloat16* lp,
                                         size_t i, float v0, float v1) {
    __nv_bfloat16 h0 = __float2bfloat16(v0), h1 = __float2bfloat16(v1);
    __nv_bfloat16 l0 = __float2bfloat16(v0 - __bfloat162float(h0));
    __nv_bfloat16 l1 = __float2bfloat16(v1 - __bfloat162float(h1));
    __nv_bfloat162 hh(h0, h1), ll(l0, l1);
    *(uint32_t*)(hp + i) = *(uint32_t*)&hh;
    *(uint32_t*)(lp + i) = *(uint32_t*)&ll;
}

#define CP_ASYNC16(dst, src) \
    asm volatile("cp.async.ca.shared.global [%0], [%1], 16;" \
                 :: "r"(dst), "l"(src) : "memory")
#define CP_COMMIT() asm volatile("cp.async.commit_group;" ::: "memory")

// ---------------------------------------------------------------------------
// Prepass kernels
// ---------------------------------------------------------------------------
__global__ void split_bf16(const float4* __restrict__ in,
                           __nv_bfloat16* __restrict__ hi,
                           __nv_bfloat16* __restrict__ lo, int n4)
{
    int i = blockIdx.x * blockDim.x + threadIdx.x;
    if (i >= n4) return;
    float4 v = in[i];
    __nv_bfloat16 h0 = __float2bfloat16(v.x), h1 = __float2bfloat16(v.y);
    __nv_bfloat16 h2 = __float2bfloat16(v.z), h3 = __float2bfloat16(v.w);
    __nv_bfloat16 l0 = __float2bfloat16(v.x - __bfloat162float(h0));
    __nv_bfloat16 l1 = __float2bfloat16(v.y - __bfloat162float(h1));
    __nv_bfloat16 l2 = __float2bfloat16(v.z - __bfloat162float(h2));
    __nv_bfloat16 l3 = __float2bfloat16(v.w - __bfloat162float(h3));
    __nv_bfloat162 hp0(h0, h1), hp1(h2, h3), lp0(l0, l1), lp1(l2, l3);
    uint2 hw, lw;
    hw.x = *(uint32_t*)&hp0; hw.y = *(uint32_t*)&hp1;
    lw.x = *(uint32_t*)&lp0; lw.y = *(uint32_t*)&lp1;
    *(uint2*)(hi + (size_t)i * 4) = hw;
    *(uint2*)(lo + (size_t)i * 4) = lw;
}

__global__ void transpose_split(const float* __restrict__ in,
                                __nv_bfloat16* __restrict__ hiT,
                                __nv_bfloat16* __restrict__ loT,
                                int Kdim, int Cdim)
{
    __shared__ float tile[32][33];
    int bx = blockIdx.x * 32;
    int by = blockIdx.y * 32;
    int x = threadIdx.x, y = threadIdx.y;
    #pragma unroll
    for (int j = 0; j < 4; ++j)
        tile[y + j * 8][x] = in[(size_t)(by + y + j * 8) * Cdim + bx + x];
    __syncthreads();
    #pragma unroll
    for (int j = 0; j < 4; ++j) {
        float v = tile[x][y + j * 8];
        __nv_bfloat16 h = __float2bfloat16(v);
        __nv_bfloat16 l = __float2bfloat16(v - __bfloat162float(h));
        size_t o = (size_t)(bx + y + j * 8) * Kdim + by + x;
        hiT[o] = h;
        loT[o] = l;
    }
}

// ---------------------------------------------------------------------------
// GEMM: 128x128 tile, BK=32, 8 warps, split-bf16 3-term.
// MODE 0: fp32 out + bias. MODE 1: QKV epilogue (scale+split Q/K bf16, V half).
// ---------------------------------------------------------------------------
#define PLANE_B   10240
#define PLANE_E   5120
#define STAGE_B   40960
#define GEMM_SMEM (2 * STAGE_B)

template<int MODE>
__global__ __launch_bounds__(256, 1) void mma_gemm_t(
    const __nv_bfloat16* __restrict__ Ahi, const __nv_bfloat16* __restrict__ Alo,
    const __nv_bfloat16* __restrict__ BThi, const __nv_bfloat16* __restrict__ BTlo,
    const float* __restrict__ bias, float* __restrict__ C,
    __nv_bfloat16* __restrict__ qh, __nv_bfloat16* __restrict__ ql,
    __nv_bfloat16* __restrict__ kh, __nv_bfloat16* __restrict__ kl,
    __half* __restrict__ vh,
    int N, int K)
{
    extern __shared__ __align__(16) char sm[];
    const uint32_t smb = smem_to_u32(sm);

    const int tid  = threadIdx.x;
    const int warp = tid >> 5;
    const int lane = tid & 31;
    const int wm   = warp >> 2;
    const int wn   = warp & 3;
    const int bm   = blockIdx.y * 128;
    const int bn   = blockIdx.x * 128;

    const int r0 = tid >> 2;
    const int c8 = (tid & 3) * 8;

    const int arow = (lane & 15);
    const int ak8  = ((lane >> 4) & 1) << 3;
    const int brow = (lane & 7);
    const int bk8  = ((lane >> 3) & 1) << 3;

    float acc[4][4][4];
    #pragma unroll
    for (int i = 0; i < 4; ++i)
        #pragma unroll
        for (int j = 0; j < 4; ++j)
            #pragma unroll
            for (int k = 0; k < 4; ++k) acc[i][j][k] = 0.0f;

    uint4 v[8];
    auto gload = [&](int t) {
        size_t ka = (size_t)t * 32 + c8;
        v[0] = *(const uint4*)(Ahi  + (size_t)(bm + r0)      * K + ka);
        v[1] = *(const uint4*)(Ahi  + (size_t)(bm + r0 + 64) * K + ka);
        v[2] = *(const uint4*)(Alo  + (size_t)(bm + r0)      * K + ka);
        v[3] = *(const uint4*)(Alo  + (size_t)(bm + r0 + 64) * K + ka);
        v[4] = *(const uint4*)(BThi + (size_t)(bn + r0)      * K + ka);
        v[5] = *(const uint4*)(BThi + (size_t)(bn + r0 + 64) * K + ka);
        v[6] = *(const uint4*)(BTlo + (size_t)(bn + r0)      * K + ka);
        v[7] = *(const uint4*)(BTlo + (size_t)(bn + r0 + 64) * K + ka);
    };
    auto sstore = [&](int s) {
        __nv_bfloat16* st = (__nv_bfloat16*)(sm + s * STAGE_B);
        #pragma unroll
        for (int p = 0; p < 4; ++p) {
            *(uint4*)(st + p * PLANE_E + (size_t)r0 * 40 + c8)        = v[2 * p];
            *(uint4*)(st + p * PLANE_E + (size_t)(r0 + 64) * 40 + c8) = v[2 * p + 1];
        }
    };

    const int nstage = K >> 5;

    gload(0);
    sstore(0);
    __syncthreads();

    for (int t = 0; t < nstage; ++t) {
        const int s = t & 1;
        if (t + 1 < nstage) gload(t + 1);

        const uint32_t pAh = smb + s * STAGE_B;
        const uint32_t pAl = pAh + PLANE_B;
        const uint32_t pBh = pAh + 2 * PLANE_B;
        const uint32_t pBl = pAh + 3 * PLANE_B;

        #pragma unroll
        for (int kc = 0; kc < 32; kc += 16) {
            uint32_t bh[4][2], bl[4][2];
            #pragma unroll
            for (int ntl = 0; ntl < 4; ++ntl) {
                uint32_t boff = (uint32_t)(wn * 32 + ntl * 8 + brow) * 80
                              + (uint32_t)(kc + bk8) * 2;
                ldsm_x2(bh[ntl], pBh + boff);
                ldsm_x2(bl[ntl], pBl + boff);
            }
            #pragma unroll
            for (int mt = 0; mt < 4; ++mt) {
                uint32_t aoff = (uint32_t)(wm * 64 + mt * 16 + arow) * 80
                              + (uint32_t)(kc + ak8) * 2;
                uint32_t ah[4], al[4];
                ldsm_x4(ah, pAh + aoff);
                ldsm_x4(al, pAl + aoff);
                #pragma unroll
                for (int ntl = 0; ntl < 4; ++ntl) {
                    mma_bf16(acc[mt][ntl], ah, bh[ntl]);
                    mma_bf16(acc[mt][ntl], ah, bl[ntl]);
                    mma_bf16(acc[mt][ntl], al, bh[ntl]);
                }
            }
        }

        if (t + 1 < nstage) sstore(s ^ 1);
        __syncthreads();
    }

    // epilogue
    const int g   = lane >> 2;
    const int tig = lane & 3;
    const int seg = bn >> 10;   // MODE 1: 0=Q, 1=K, 2=V (uniform per block)
    #pragma unroll
    for (int ntl = 0; ntl < 4; ++ntl) {
        int colg = bn + wn * 32 + ntl * 8 + tig * 2;
        float b0 = __ldg(bias + colg);
        float b1 = __ldg(bias + colg + 1);
        #pragma unroll
        for (int mt = 0; mt < 4; ++mt) {
            int row = bm + wm * 64 + mt * 16 + g;
            float v0 = acc[mt][ntl][0] + b0;
            float v1 = acc[mt][ntl][1] + b1;
            float v2 = acc[mt][ntl][2] + b0;
            float v3 = acc[mt][ntl][3] + b1;
            if (MODE == 0) {
                float2 o0, o1;
                o0.x = v0; o0.y = v1;
                o1.x = v2; o1.y = v3;
                *(float2*)&C[(size_t)row * N + colg]       = o0;
                *(float2*)&C[(size_t)(row + 8) * N + colg] = o1;
            } else {
                int c = colg & 1023;
                size_t i0 = (size_t)row * NX + c;
                size_t i1 = (size_t)(row + 8) * NX + c;
                if (seg == 0) {
                    st_split(qh, ql, i0, v0 * CSC, v1 * CSC);
                    st_split(qh, ql, i1, v2 * CSC, v3 * CSC);
                } else if (seg == 1) {
                    st_split(kh, kl, i0, v0, v1);
                    st_split(kh, kl, i1, v2, v3);
                } else {
                    __half2 h0 = __floats2half2_rn(v0, v1);
                    __half2 h1 = __floats2half2_rn(v2, v3);
                    *(uint32_t*)(vh + i0) = *(uint32_t*)&h0;
                    *(uint32_t*)(vh + i1) = *(uint32_t*)&h1;
                }
            }
        }
    }
}

// ---------------------------------------------------------------------------
// Tensor-core flash attention (causal, log2-domain softmax).
// Block = (128 queries, head, batch), 8 warps x 16 query rows.
// KV tiles of 128 keys, cp.async double-buffered.
// Smem (bytes): Qh 18432 | Ql 18432 | 2 x [Kh 18432 | Kl 18432 | Vh 18432]
// Row pad: 72 elems (144B) -> conflict-free ldmatrix.
// ---------------------------------------------------------------------------
#define FL_SMEM (36864 + 2 * 55296)

__global__ __launch_bounds__(256, 1) void flash_mma(
    const __nv_bfloat16* __restrict__ qh, const __nv_bfloat16* __restrict__ ql,
    const __nv_bfloat16* __restrict__ kh, const __nv_bfloat16* __restrict__ kl,
    const __half* __restrict__ vh,
    __nv_bfloat16* __restrict__ outh, __nv_bfloat16* __restrict__ outl)
{
    extern __shared__ __align__(16) char sm[];
    const uint32_t smb = smem_to_u32(sm);
    const uint32_t sQH = smb, sQL = smb + 18432;
    const uint32_t sKV = smb + 36864;

    const int tid  = threadIdx.x;
    const int lane = tid & 31;
    const int w    = tid >> 5;
    const int qt   = blockIdx.x;
    const int h    = blockIdx.y;
    const int b    = blockIdx.z;
    const int q0   = qt * 128;
    const size_t rowbase = (size_t)b * SS;
    const int colb = h * HD;

    // issue KV tile loads via cp.async (3 planes x 1024 16B-chunks)
    auto issue_kv = [&](int kt, int s) {
        const uint32_t dst = sKV + s * 55296;
        const size_t krow0 = rowbase + (size_t)kt * 128;
        #pragma unroll
        for (int i = 0; i < 4; ++i) {
            int c = (i << 8) + tid;
            int r = c >> 3, ch = c & 7;
            size_t go = (krow0 + r) * NX + colb + ch * 8;
            uint32_t so = (uint32_t)(r * 144 + ch * 16);
            CP_ASYNC16(dst + so,         (const char*)kh + go * 2);
            CP_ASYNC16(dst + 18432 + so, (const char*)kl + go * 2);
            CP_ASYNC16(dst + 36864 + so, (const char*)vh + go * 2);
        }
    };

    issue_kv(0, 0);
    CP_COMMIT();

    // load Q tile (both planes) into smem
    {
        int r = tid >> 1;
        int d0 = (tid & 1) * 32;
        const __nv_bfloat16* gq = qh + (rowbase + q0 + r) * NX + colb + d0;
        const __nv_bfloat16* gl = ql + (rowbase + q0 + r) * NX + colb + d0;
        uint32_t so = (uint32_t)(r * 144 + d0 * 2);
        #pragma unroll
        for (int i = 0; i < 4; ++i) {
            *(uint4*)(sm + (sQH - smb) + so + i * 16) = *(const uint4*)(gq + i * 8);
            *(uint4*)(sm + (sQL - smb) + so + i * 16) = *(const uint4*)(gl + i * 8);
        }
    }

    float O[8][4];
    #pragma unroll
    for (int i = 0; i < 8; ++i)
        #pragma unroll
        for (int j = 0; j < 4; ++j) O[i][j] = 0.0f;
    float mprev_g = -1e30f, mprev_h = -1e30f;
    float lsum_g = 0.0f, lsum_h = 0.0f;

    const uint32_t ones[2] = {0x3C003C00u, 0x3C003C00u};

    for (int kt = 0; kt <= qt; ++kt) {
        if (kt < qt) {
            issue_kv(kt + 1, (kt + 1) & 1);
            CP_COMMIT();
            asm volatile("cp.async.wait_group 1;" ::: "memory");
        } else {
            asm volatile("cp.async.wait_group 0;" ::: "memory");
        }
        __syncthreads();

        const bool diag = (kt == qt);
        const int s = kt & 1;
        const uint32_t bKH = sKV + s * 55296;
        const uint32_t bKL = bKH + 18432;
        const uint32_t bVH = bKH + 36864;
        const int nt_max = diag ? 2 * w + 2 : 16;
        const int kc_max = diag ? w + 1 : 8;

        // ---- S = Q K^T (3-term split bf16) ----
        float sc[16][4];
        #pragma unroll
        for (int i = 0; i < 16; ++i)
            #pragma unroll
            for (int j = 0; j < 4; ++j) sc[i][j] = 0.0f;

        #pragma unroll
        for (int kc = 0; kc < 4; ++kc) {
            uint32_t aoff = (uint32_t)(w * 16 + (lane & 15)) * 144
                          + (uint32_t)(kc * 16 + ((lane >> 4) & 1) * 8) * 2;
            uint32_t ah[4], al[4];
            ldsm_x4(ah, sQH + aoff);
            ldsm_x4(al, sQL + aoff);
            #pragma unroll
            for (int nt0 = 0; nt0 < 16; nt0 += 2) {
                if (nt0 < nt_max) {
                    uint32_t boff = (uint32_t)(nt0 * 8 + (lane & 7)
                                  + ((lane >> 4) & 1) * 8) * 144
                                  + (uint32_t)(kc * 16 + ((lane >> 3) & 1) * 8) * 2;
                    uint32_t bh[4], bl[4];
                    ldsm_x4(bh, bKH + boff);
                    ldsm_x4(bl, bKL + boff);
                    mma_bf16(sc[nt0], ah, &bh[0]);
                    mma_bf16(sc[nt0], ah, &bl[0]);
                    mma_bf16(sc[nt0], al, &bh[0]);
                    mma_bf16(sc[nt0 + 1], ah, &bh[2]);
                    mma_bf16(sc[nt0 + 1], ah, &bl[2]);
                    mma_bf16(sc[nt0 + 1], al, &bh[2]);
                }
            }
        }

        // ---- causal mask (diag tile) ----
        if (diag) {
            int rg = q0 + w * 16 + (lane >> 2);
            #pragma unroll
            for (int nt = 0; nt < 16; ++nt) {
                if (nt < nt_max) {
                    int cg = q0 + nt * 8 + (lane & 3) * 2;
                    if (cg     > rg)     sc[nt][0] = -1e30f;
                    if (cg + 1 > rg)     sc[nt][1] = -1e30f;
                    if (cg     > rg + 8) sc[nt][2] = -1e30f;
                    if (cg + 1 > rg + 8) sc[nt][3] = -1e30f;
                }
            }
        }

        // ---- online softmax (log2 domain) ----
        float mg = -1e30f, mh = -1e30f;
        #pragma unroll
        for (int nt = 0; nt < 16; ++nt) {
            if (nt < nt_max) {
                mg = fmaxf(mg, fmaxf(sc[nt][0], sc[nt][1]));
                mh = fmaxf(mh, fmaxf(sc[nt][2], sc[nt][3]));
            }
        }
        mg = fmaxf(mg, __shfl_xor_sync(0xffffffffu, mg, 1));
        mg = fmaxf(mg, __shfl_xor_sync(0xffffffffu, mg, 2));
        mh = fmaxf(mh, __shfl_xor_sync(0xffffffffu, mh, 1));
        mh = fmaxf(mh, __shfl_xor_sync(0xffffffffu, mh, 2));
        float mng = fmaxf(mprev_g, mg);
        float mnh = fmaxf(mprev_h, mh);
        float ag = ex2f(mprev_g - mng);
        float ah2 = ex2f(mprev_h - mnh);
        mprev_g = mng; mprev_h = mnh;
        lsum_g *= ag; lsum_h *= ah2;
        #pragma unroll
        for (int dt = 0; dt < 8; ++dt) {
            O[dt][0] *= ag;  O[dt][1] *= ag;
            O[dt][2] *= ah2; O[dt][3] *= ah2;
        }

        // ---- P = 2^(S - m) as packed half2 (A-fragment format) ----
        uint32_t p[16][2];
        #pragma unroll
        for (int nt = 0; nt < 16; ++nt) {
            if (nt < nt_max) {
                p[nt][0] = ex2_pack(sc[nt][1] - mng, sc[nt][0] - mng);
                p[nt][1] = ex2_pack(sc[nt][3] - mnh, sc[nt][2] - mnh);
            }
        }

        // ---- O += P V ; lsum += P @ ones (tensor) ----
        float ss[4] = {0.0f, 0.0f, 0.0f, 0.0f};
        #pragma unroll
        for (int kc2 = 0; kc2 < 8; ++kc2) {
            if (kc2 < kc_max) {
                uint32_t a[4] = { p[2 * kc2][0], p[2 * kc2][1],
                                  p[2 * kc2 + 1][0], p[2 * kc2 + 1][1] };
                mma_f16(ss, a, ones);
                #pragma unroll
                for (int dt0 = 0; dt0 < 8; dt0 += 2) {
                    uint32_t voff = (uint32_t)(kc2 * 16 + (lane & 7)
                                  + ((lane >> 3) & 1) * 8) * 144
                                  + (uint32_t)(dt0 * 8 + ((lane >> 4) & 1) * 8) * 2;
                    uint32_t v4[4];
                    ldsm_x4_t(v4, bVH + voff);
                    mma_f16(O[dt0],     a, &v4[0]);
                    mma_f16(O[dt0 + 1], a, &v4[2]);
                }
            }
        }
        lsum_g += ss[0];
        lsum_h += ss[2];

        __syncthreads();
    }

    // ---- epilogue: normalize, split-bf16 store (merged heads) ----
    float ig = 1.0f / lsum_g;
    float ih = 1.0f / lsum_h;
    int r0 = q0 + w * 16 + (lane >> 2);
    size_t base0 = (rowbase + r0) * NX + colb + (lane & 3) * 2;
    size_t base1 = base0 + (size_t)8 * NX;
    #pragma unroll
    for (int dt = 0; dt < 8; ++dt) {
        st_split(outh, outl, base0 + dt * 8, O[dt][0] * ig, O[dt][1] * ig);
        st_split(outh, outl, base1 + dt * 8, O[dt][2] * ih, O[dt][3] * ih);
    }
}

// ---------------------------------------------------------------------------
extern "C" void kernel_launch(void* const* d_in, const int* in_sizes, int n_in,
                              void* d_out, int out_size)
{
    const float* x      = (const float*)d_in[0];
    const float* w_attn = (const float*)d_in[1];
    const float* b_attn = (const float*)d_in[2];
    const float* w_proj = (const float*)d_in[3];
    const float* b_proj = (const float*)d_in[4];
    float* out = (float*)d_out;

    __nv_bfloat16 *xhi, *xlo, *wahi, *walo, *wphi, *wplo;
    __nv_bfloat16 *qh, *ql, *kh, *kl, *ahi, *alo;
    __half *vh;
    cudaGetSymbolAddress((void**)&xhi,  g_xhi);
    cudaGetSymbolAddress((void**)&xlo,  g_xlo);
    cudaGetSymbolAddress((void**)&wahi, g_wahi);
    cudaGetSymbolAddress((void**)&walo, g_walo);
    cudaGetSymbolAddress((void**)&wphi, g_wphi);
    cudaGetSymbolAddress((void**)&wplo, g_wplo);
    cudaGetSymbolAddress((void**)&qh,   g_qh);
    cudaGetSymbolAddress((void**)&ql,   g_ql);
    cudaGetSymbolAddress((void**)&kh,   g_kh);
    cudaGetSymbolAddress((void**)&kl,   g_kl);
    cudaGetSymbolAddress((void**)&vh,   g_vh);
    cudaGetSymbolAddress((void**)&ahi,  g_ahi);
    cudaGetSymbolAddress((void**)&alo,  g_alo);

    // prepass
    {
        int n4 = BB * SS * NX / 4;
        split_bf16<<<(n4 + 255) / 256, 256>>>((const float4*)x, xhi, xlo, n4);
        transpose_split<<<dim3(3 * NX / 32, NX / 32), dim3(32, 8)>>>(
            w_attn, wahi, walo, NX, 3 * NX);
        transpose_split<<<dim3(NX / 32, NX / 32), dim3(32, 8)>>>(
            w_proj, wphi, wplo, NX, NX);
    }

    cudaFuncSetAttribute(mma_gemm_t<0>, cudaFuncAttributeMaxDynamicSharedMemorySize,
                         GEMM_SMEM);
    cudaFuncSetAttribute(mma_gemm_t<1>, cudaFuncAttributeMaxDynamicSharedMemorySize,
                         GEMM_SMEM);
    cudaFuncSetAttribute(flash_mma, cudaFuncAttributeMaxDynamicSharedMemorySize,
                         FL_SMEM);

    // 1) QKV projection -> scaled/split Q,K (bf16) + V (half)
    {
        dim3 grid(3 * NX / 128, BB * SS / 128);
        mma_gemm_t<1><<<grid, 256, GEMM_SMEM>>>(
            xhi, xlo, wahi, walo, b_attn, nullptr,
            qh, ql, kh, kl, vh, 3 * NX, NX);
    }

    // 2) flash attention (tensor cores) -> split-bf16 merged heads
    {
        dim3 grid(SS / 128, NH, BB);
        flash_mma<<<grid, 256, FL_SMEM>>>(qh, ql, kh, kl, vh, ahi, alo);
    }

    // 3) out = attn @ w_proj + b_proj
    {
        dim3 grid(NX / 128, BB * SS / 128);
        mma_gemm_t<0><<<grid, 256, GEMM_SMEM>>>(
            ahi, alo, wphi, wplo, b_proj, out,
            nullptr, nullptr, nullptr, nullptr, nullptr, NX, NX);
    }
}

// round 5
// speedup vs baseline: 6.0173x; 2.2310x over previous
#include <cuda_runtime.h>
#include <cuda_bf16.h>
#include <cuda_fp16.h>
#include <cstdint>

// Problem constants
#define BB 8
#define SS 1024
#define NX 1024
#define NH 16
#define HD 64

// log2(e) / sqrt(64) folded into Q
#define CSC 0.18033688011112042592f

// ---------------------------------------------------------------------------
// Scratch (device globals; allocation-free rule)
// ---------------------------------------------------------------------------
__device__ __half g_xh[(size_t)BB * SS * NX];           // x in f16
__device__ __half g_wat[(size_t)3 * NX * NX];           // w_attn^T [3NX][NX] f16
__device__ __half g_wpt[(size_t)NX * NX];               // w_proj^T [NX][NX] f16
__device__ __half g_qkvh[(size_t)BB * SS * 3 * NX];     // QKV (Q pre-scaled) f16
__device__ __half g_oh[(size_t)BB * SS * NX];           // attention out f16

__device__ __forceinline__ uint32_t smem_to_u32(const void* p) {
    uint32_t a;
    asm("{ .reg .u64 t; cvta.to.shared.u64 t, %1; cvt.u32.u64 %0, t; }"
        : "=r"(a) : "l"(p));
    return a;
}

// ---------------------------------------------------------------------------
// MMA / ldmatrix / misc helpers
// ---------------------------------------------------------------------------
__device__ __forceinline__ void mma_f16(float* d, const uint32_t* a,
                                        const uint32_t* b) {
    asm volatile(
        "mma.sync.aligned.m16n8k16.row.col.f32.f16.f16.f32 "
        "{%0,%1,%2,%3}, {%4,%5,%6,%7}, {%8,%9}, {%0,%1,%2,%3};"
        : "+f"(d[0]), "+f"(d[1]), "+f"(d[2]), "+f"(d[3])
        : "r"(a[0]), "r"(a[1]), "r"(a[2]), "r"(a[3]), "r"(b[0]), "r"(b[1]));
}

__device__ __forceinline__ void ldsm_x4(uint32_t* r, uint32_t addr) {
    asm volatile("ldmatrix.sync.aligned.m8n8.x4.shared.b16 {%0,%1,%2,%3}, [%4];"
                 : "=r"(r[0]), "=r"(r[1]), "=r"(r[2]), "=r"(r[3]) : "r"(addr));
}

__device__ __forceinline__ void ldsm_x4_t(uint32_t* r, uint32_t addr) {
    asm volatile("ldmatrix.sync.aligned.m8n8.x4.trans.shared.b16 {%0,%1,%2,%3}, [%4];"
                 : "=r"(r[0]), "=r"(r[1]), "=r"(r[2]), "=r"(r[3]) : "r"(addr));
}

__device__ __forceinline__ float ex2f(float x) {
    float r;
    asm("ex2.approx.ftz.f32 %0, %1;" : "=f"(r) : "f"(x));
    return r;
}

__device__ __forceinline__ uint32_t ex2_pack(float hi, float lo) {
    uint32_t t, r;
    asm("cvt.rn.f16x2.f32 %0, %1, %2;" : "=r"(t) : "f"(hi), "f"(lo));
    asm("ex2.approx.f16x2 %0, %1;" : "=r"(r) : "r"(t));
    return r;
}

#define CP_ASYNC16(dst, src) \
    asm volatile("cp.async.cg.shared.global [%0], [%1], 16;" \
                 :: "r"(dst), "l"(src) : "memory")
#define CP_COMMIT() asm volatile("cp.async.commit_group;" ::: "memory")

// ---------------------------------------------------------------------------
// Prepass kernels
// ---------------------------------------------------------------------------
__global__ void to_f16(const float4* __restrict__ in, __half* __restrict__ out,
                       int n4)
{
    int i = blockIdx.x * blockDim.x + threadIdx.x;
    if (i >= n4) return;
    float4 v = in[i];
    __half2 a = __floats2half2_rn(v.x, v.y);
    __half2 b = __floats2half2_rn(v.z, v.w);
    uint2 w;
    w.x = *(uint32_t*)&a;
    w.y = *(uint32_t*)&b;
    *(uint2*)(out + (size_t)i * 4) = w;
}

// transpose K x C fp32 -> [C][K] f16
__global__ void transpose_f16(const float* __restrict__ in,
                              __half* __restrict__ outT, int Kdim, int Cdim)
{
    __shared__ float tile[32][33];
    int bx = blockIdx.x * 32;
    int by = blockIdx.y * 32;
    int x = threadIdx.x, y = threadIdx.y;   // 32 x 8
    #pragma unroll
    for (int j = 0; j < 4; ++j)
        tile[y + j * 8][x] = in[(size_t)(by + y + j * 8) * Cdim + bx + x];
    __syncthreads();
    #pragma unroll
    for (int j = 0; j < 4; ++j) {
        float v = tile[x][y + j * 8];
        outT[(size_t)(bx + y + j * 8) * Kdim + by + x] = __float2half(v);
    }
}

// ---------------------------------------------------------------------------
// Single-term f16 GEMM: C(MxN) = A(MxK) @ BT(NxK)^T + bias.
// 128x128 block tile, BK=64, 4-stage cp.async pipeline, 8 warps (2x4),
// warp tile 64x32. Smem row stride 72 halves (144B) -> conflict-free ldsm.
// MODE 0: fp32 out + bias.   MODE 1: f16 out + bias, xCSC on Q segment.
// ---------------------------------------------------------------------------
#define GSTAGES   4
#define GPLANE_B  18432                  // 128 * 144
#define GSTAGE_B  36864                  // A + B planes
#define GEMM_SMEM (GSTAGES * GSTAGE_B)   // 147456

template<int MODE>
__global__ __launch_bounds__(256, 1) void gemm_f16(
    const __half* __restrict__ A, const __half* __restrict__ BT,
    const float* __restrict__ bias, float* __restrict__ C,
    __half* __restrict__ H, int N, int K)
{
    extern __shared__ __align__(16) char sm[];
    const uint32_t smb = smem_to_u32(sm);

    const int tid  = threadIdx.x;
    const int lane = tid & 31;
    const int warp = tid >> 5;
    const int wm   = warp >> 2;
    const int wn   = warp & 3;
    const int bm   = blockIdx.y * 128;
    const int bn   = blockIdx.x * 128;

    auto issue = [&](int t, int s) {
        const uint32_t dst = smb + s * GSTAGE_B;
        const size_t k0 = (size_t)t * 64;
        #pragma unroll
        for (int i = 0; i < 4; ++i) {
            int c = (i << 8) + tid;
            int r = c >> 3, ch = c & 7;
            uint32_t so = (uint32_t)(r * 144 + ch * 16);
            CP_ASYNC16(dst + so,
                       (const char*)(A + (size_t)(bm + r) * K + k0 + ch * 8));
            CP_ASYNC16(dst + GPLANE_B + so,
                       (const char*)(BT + (size_t)(bn + r) * K + k0 + ch * 8));
        }
    };

    float acc[4][4][4];
    #pragma unroll
    for (int i = 0; i < 4; ++i)
        #pragma unroll
        for (int j = 0; j < 4; ++j)
            #pragma unroll
            for (int k = 0; k < 4; ++k) acc[i][j][k] = 0.0f;

    const int nstage = K >> 6;   // 16

    #pragma unroll
    for (int ps = 0; ps < GSTAGES - 1; ++ps) {
        if (ps < nstage) issue(ps, ps);
        CP_COMMIT();
    }

    for (int t = 0; t < nstage; ++t) {
        asm volatile("cp.async.wait_group %0;" :: "n"(GSTAGES - 2) : "memory");
        __syncthreads();

        const uint32_t pA = smb + (t & (GSTAGES - 1)) * GSTAGE_B;
        const uint32_t pB = pA + GPLANE_B;

        #pragma unroll
        for (int kc = 0; kc < 4; ++kc) {
            uint32_t b[2][4];
            #pragma unroll
            for (int pr = 0; pr < 2; ++pr) {
                uint32_t boff = (uint32_t)(wn * 32 + pr * 16
                              + ((lane >> 4) & 1) * 8 + (lane & 7)) * 144
                              + (uint32_t)(kc * 16 + ((lane >> 3) & 1) * 8) * 2;
                ldsm_x4(b[pr], pB + boff);
            }
            #pragma unroll
            for (int mt = 0; mt < 4; ++mt) {
                uint32_t aoff = (uint32_t)(wm * 64 + mt * 16 + (lane & 15)) * 144
                              + (uint32_t)(kc * 16 + ((lane >> 4) & 1) * 8) * 2;
                uint32_t a[4];
                ldsm_x4(a, pA + aoff);
                mma_f16(acc[mt][0], a, &b[0][0]);
                mma_f16(acc[mt][1], a, &b[0][2]);
                mma_f16(acc[mt][2], a, &b[1][0]);
                mma_f16(acc[mt][3], a, &b[1][2]);
            }
        }

        if (t + GSTAGES - 1 < nstage)
            issue(t + GSTAGES - 1, (t + GSTAGES - 1) & (GSTAGES - 1));
        CP_COMMIT();
    }

    // epilogue
    const int g   = lane >> 2;
    const int tig = lane & 3;
    const float scale = (MODE == 1 && (bn >> 10) == 0) ? CSC : 1.0f;
    #pragma unroll
    for (int ntl = 0; ntl < 4; ++ntl) {
        int colg = bn + wn * 32 + ntl * 8 + tig * 2;
        float b0 = __ldg(bias + colg);
        float b1 = __ldg(bias + colg + 1);
        #pragma unroll
        for (int mt = 0; mt < 4; ++mt) {
            int row = bm + wm * 64 + mt * 16 + g;
            float v0 = acc[mt][ntl][0] + b0;
            float v1 = acc[mt][ntl][1] + b1;
            float v2 = acc[mt][ntl][2] + b0;
            float v3 = acc[mt][ntl][3] + b1;
            if (MODE == 0) {
                float2 o0, o1;
                o0.x = v0; o0.y = v1;
                o1.x = v2; o1.y = v3;
                *(float2*)&C[(size_t)row * N + colg]       = o0;
                *(float2*)&C[(size_t)(row + 8) * N + colg] = o1;
            } else {
                __half2 h0 = __floats2half2_rn(v0 * scale, v1 * scale);
                __half2 h1 = __floats2half2_rn(v2 * scale, v3 * scale);
                *(uint32_t*)(H + (size_t)row * N + colg)       = *(uint32_t*)&h0;
                *(uint32_t*)(H + (size_t)(row + 8) * N + colg) = *(uint32_t*)&h1;
            }
        }
    }
}

// ---------------------------------------------------------------------------
// Tensor-core flash attention (causal, log2-domain softmax), all-f16 operands.
// Block = (128 queries, head, batch), 8 warps x 16 query rows.
// KV tiles of 128 keys, cp.async double-buffered.
// Smem: Q 18432 | 2 x [K 18432 | V 18432] = 92160 bytes.
// ---------------------------------------------------------------------------
#define FL_STAGE 36864
#define FL_SMEM  (18432 + 2 * FL_STAGE)

__global__ __launch_bounds__(256, 1) void flash_mma(
    const __half* __restrict__ qkv, __half* __restrict__ Og)
{
    extern __shared__ __align__(16) char sm[];
    const uint32_t smb = smem_to_u32(sm);
    const uint32_t sQ  = smb;
    const uint32_t sKV = smb + 18432;

    const int tid  = threadIdx.x;
    const int lane = tid & 31;
    const int w    = tid >> 5;
    const int qt   = blockIdx.x;
    const int h    = blockIdx.y;
    const int b    = blockIdx.z;
    const int q0   = qt * 128;
    const size_t rowbase = (size_t)b * SS;
    const int colb = h * HD;

    auto issue_kv = [&](int kt, int s) {
        const uint32_t dst = sKV + s * FL_STAGE;
        const size_t krow0 = rowbase + (size_t)kt * 128;
        #pragma unroll
        for (int i = 0; i < 4; ++i) {
            int c = (i << 8) + tid;
            int r = c >> 3, ch = c & 7;
            size_t go = (krow0 + r) * (3 * NX) + colb + ch * 8;
            uint32_t so = (uint32_t)(r * 144 + ch * 16);
            CP_ASYNC16(dst + so,         (const char*)(qkv + NX + go));
            CP_ASYNC16(dst + 18432 + so, (const char*)(qkv + 2 * NX + go));
        }
    };

    issue_kv(0, 0);
    CP_COMMIT();

    // load Q tile into smem (f16, single plane)
    {
        int r  = tid >> 1;
        int d0 = (tid & 1) * 32;
        const __half* gq = qkv + (rowbase + q0 + r) * (3 * NX) + colb + d0;
        uint32_t so = (uint32_t)(r * 144 + d0 * 2);
        #pragma unroll
        for (int i = 0; i < 4; ++i)
            *(uint4*)(sm + so + i * 16) = *(const uint4*)(gq + i * 8);
    }

    float O[8][4];
    #pragma unroll
    for (int i = 0; i < 8; ++i)
        #pragma unroll
        for (int j = 0; j < 4; ++j) O[i][j] = 0.0f;
    float mprev_g = -1e30f, mprev_h = -1e30f;
    float lsum_g = 0.0f, lsum_h = 0.0f;

    const uint32_t ones[2] = {0x3C003C00u, 0x3C003C00u};

    for (int kt = 0; kt <= qt; ++kt) {
        if (kt < qt) {
            issue_kv(kt + 1, (kt + 1) & 1);
            CP_COMMIT();
            asm volatile("cp.async.wait_group 1;" ::: "memory");
        } else {
            asm volatile("cp.async.wait_group 0;" ::: "memory");
        }
        __syncthreads();

        const bool diag = (kt == qt);
        const int s = kt & 1;
        const uint32_t bK = sKV + s * FL_STAGE;
        const uint32_t bV = bK + 18432;
        const int nt_max = diag ? 2 * w + 2 : 16;
        const int kc_max = diag ? w + 1 : 8;

        // ---- S = Q K^T (single-term f16) ----
        float sc[16][4];
        #pragma unroll
        for (int i = 0; i < 16; ++i)
            #pragma unroll
            for (int j = 0; j < 4; ++j) sc[i][j] = 0.0f;

        #pragma unroll
        for (int kc = 0; kc < 4; ++kc) {
            uint32_t aoff = (uint32_t)(w * 16 + (lane & 15)) * 144
                          + (uint32_t)(kc * 16 + ((lane >> 4) & 1) * 8) * 2;
            uint32_t a[4];
            ldsm_x4(a, sQ + aoff);
            #pragma unroll
            for (int nt0 = 0; nt0 < 16; nt0 += 2) {
                if (nt0 < nt_max) {
                    uint32_t boff = (uint32_t)(nt0 * 8 + (lane & 7)
                                  + ((lane >> 4) & 1) * 8) * 144
                                  + (uint32_t)(kc * 16 + ((lane >> 3) & 1) * 8) * 2;
                    uint32_t bb[4];
                    ldsm_x4(bb, bK + boff);
                    mma_f16(sc[nt0],     a, &bb[0]);
                    mma_f16(sc[nt0 + 1], a, &bb[2]);
                }
            }
        }

        // ---- causal mask (diag tile) ----
        if (diag) {
            int rg = q0 + w * 16 + (lane >> 2);
            #pragma unroll
            for (int nt = 0; nt < 16; ++nt) {
                if (nt < nt_max) {
                    int cg = q0 + nt * 8 + (lane & 3) * 2;
                    if (cg     > rg)     sc[nt][0] = -1e30f;
                    if (cg + 1 > rg)     sc[nt][1] = -1e30f;
                    if (cg     > rg + 8) sc[nt][2] = -1e30f;
                    if (cg + 1 > rg + 8) sc[nt][3] = -1e30f;
                }
            }
        }

        // ---- online softmax (log2 domain) ----
        float mg = -1e30f, mh = -1e30f;
        #pragma unroll
        for (int nt = 0; nt < 16; ++nt) {
            if (nt < nt_max) {
                mg = fmaxf(mg, fmaxf(sc[nt][0], sc[nt][1]));
                mh = fmaxf(mh, fmaxf(sc[nt][2], sc[nt][3]));
            }
        }
        mg = fmaxf(mg, __shfl_xor_sync(0xffffffffu, mg, 1));
        mg = fmaxf(mg, __shfl_xor_sync(0xffffffffu, mg, 2));
        mh = fmaxf(mh, __shfl_xor_sync(0xffffffffu, mh, 1));
        mh = fmaxf(mh, __shfl_xor_sync(0xffffffffu, mh, 2));
        float mng = fmaxf(mprev_g, mg);
        float mnh = fmaxf(mprev_h, mh);
        float ag  = ex2f(mprev_g - mng);
        float ah2 = ex2f(mprev_h - mnh);
        mprev_g = mng; mprev_h = mnh;
        lsum_g *= ag; lsum_h *= ah2;
        #pragma unroll
        for (int dt = 0; dt < 8; ++dt) {
            O[dt][0] *= ag;  O[dt][1] *= ag;
            O[dt][2] *= ah2; O[dt][3] *= ah2;
        }

        // ---- P = 2^(S - m) packed half2 (A-fragment format) ----
        uint32_t p[16][2];
        #pragma unroll
        for (int nt = 0; nt < 16; ++nt) {
            if (nt < nt_max) {
                p[nt][0] = ex2_pack(sc[nt][1] - mng, sc[nt][0] - mng);
                p[nt][1] = ex2_pack(sc[nt][3] - mnh, sc[nt][2] - mnh);
            }
        }

        // ---- O += P V ; lsum += P @ ones ----
        float ssum[4] = {0.0f, 0.0f, 0.0f, 0.0f};
        #pragma unroll
        for (int kc2 = 0; kc2 < 8; ++kc2) {
            if (kc2 < kc_max) {
                uint32_t a[4] = { p[2 * kc2][0], p[2 * kc2][1],
                                  p[2 * kc2 + 1][0], p[2 * kc2 + 1][1] };
                mma_f16(ssum, a, ones);
                #pragma unroll
                for (int dt0 = 0; dt0 < 8; dt0 += 2) {
                    uint32_t voff = (uint32_t)(kc2 * 16 + (lane & 7)
                                  + ((lane >> 3) & 1) * 8) * 144
                                  + (uint32_t)(dt0 * 8 + ((lane >> 4) & 1) * 8) * 2;
                    uint32_t v4[4];
                    ldsm_x4_t(v4, bV + voff);
                    mma_f16(O[dt0],     a, &v4[0]);
                    mma_f16(O[dt0 + 1], a, &v4[2]);
                }
            }
        }
        lsum_g += ssum[0];
        lsum_h += ssum[2];

        __syncthreads();
    }

    // ---- epilogue: normalize, f16 store (merged heads) ----
    float ig = 1.0f / lsum_g;
    float ih = 1.0f / lsum_h;
    int r0 = q0 + w * 16 + (lane >> 2);
    size_t base0 = (rowbase + r0) * NX + colb + (lane & 3) * 2;
    size_t base1 = base0 + (size_t)8 * NX;
    #pragma unroll
    for (int dt = 0; dt < 8; ++dt) {
        __half2 o0 = __floats2half2_rn(O[dt][0] * ig, O[dt][1] * ig);
        __half2 o1 = __floats2half2_rn(O[dt][2] * ih, O[dt][3] * ih);
        *(uint32_t*)(Og + base0 + dt * 8) = *(uint32_t*)&o0;
        *(uint32_t*)(Og + base1 + dt * 8) = *(uint32_t*)&o1;
    }
}

// ---------------------------------------------------------------------------
extern "C" void kernel_launch(void* const* d_in, const int* in_sizes, int n_in,
                              void* d_out, int out_size)
{
    const float* x      = (const float*)d_in[0];
    const float* w_attn = (const float*)d_in[1];
    const float* b_attn = (const float*)d_in[2];
    const float* w_proj = (const float*)d_in[3];
    const float* b_proj = (const float*)d_in[4];
    float* out = (float*)d_out;

    __half *xh, *wat, *wpt, *qkvh, *oh;
    cudaGetSymbolAddress((void**)&xh,   g_xh);
    cudaGetSymbolAddress((void**)&wat,  g_wat);
    cudaGetSymbolAddress((void**)&wpt,  g_wpt);
    cudaGetSymbolAddress((void**)&qkvh, g_qkvh);
    cudaGetSymbolAddress((void**)&oh,   g_oh);

    // prepass
    {
        int n4 = BB * SS * NX / 4;
        to_f16<<<(n4 + 255) / 256, 256>>>((const float4*)x, xh, n4);
        transpose_f16<<<dim3(3 * NX / 32, NX / 32), dim3(32, 8)>>>(
            w_attn, wat, NX, 3 * NX);
        transpose_f16<<<dim3(NX / 32, NX / 32), dim3(32, 8)>>>(
            w_proj, wpt, NX, NX);
    }

    cudaFuncSetAttribute(gemm_f16<0>, cudaFuncAttributeMaxDynamicSharedMemorySize,
                         GEMM_SMEM);
    cudaFuncSetAttribute(gemm_f16<1>, cudaFuncAttributeMaxDynamicSharedMemorySize,
                         GEMM_SMEM);
    cudaFuncSetAttribute(flash_mma, cudaFuncAttributeMaxDynamicSharedMemorySize,
                         FL_SMEM);

    // 1) QKV projection -> f16 qkv (Q pre-scaled by CSC)
    {
        dim3 grid(3 * NX / 128, BB * SS / 128);   // 24 x 64
        gemm_f16<1><<<grid, 256, GEMM_SMEM>>>(
            xh, wat, b_attn, nullptr, qkvh, 3 * NX, NX);
    }

    // 2) flash attention -> f16 merged heads
    {
        dim3 grid(SS / 128, NH, BB);
        flash_mma<<<grid, 256, FL_SMEM>>>(qkvh, oh);
    }

    // 3) out = O @ w_proj + b_proj (fp32 out)
    {
        dim3 grid(NX / 128, BB * SS / 128);       // 8 x 64
        gemm_f16<0><<<grid, 256, GEMM_SMEM>>>(
            oh, wpt, b_proj, out, nullptr, NX, NX);
    }
}

// round 6
// speedup vs baseline: 6.1880x; 1.0284x over previous
#include <cuda_runtime.h>
#include <cuda_bf16.h>
#include <cuda_fp16.h>
#include <cstdint>

// Problem constants
#define BB 8
#define SS 1024
#define NX 1024
#define NH 16
#define HD 64

// log2(e) / sqrt(64) folded into Q
#define CSC 0.18033688011112042592f

// ---------------------------------------------------------------------------
// Scratch (device globals; allocation-free rule)
// ---------------------------------------------------------------------------
__device__ __half g_xh[(size_t)BB * SS * NX];           // x in f16
__device__ __half g_wat[(size_t)3 * NX * NX];           // w_attn^T [3NX][NX] f16
__device__ __half g_wpt[(size_t)NX * NX];               // w_proj^T [NX][NX] f16
__device__ __half g_qkvh[(size_t)BB * SS * 3 * NX];     // QKV (Q pre-scaled) f16
__device__ __half g_oh[(size_t)BB * SS * NX];           // attention out f16

__device__ __forceinline__ uint32_t smem_to_u32(const void* p) {
    uint32_t a;
    asm("{ .reg .u64 t; cvta.to.shared.u64 t, %1; cvt.u32.u64 %0, t; }"
        : "=r"(a) : "l"(p));
    return a;
}

// ---------------------------------------------------------------------------
// MMA / ldmatrix / misc helpers
// ---------------------------------------------------------------------------
__device__ __forceinline__ void mma_f16(float* d, const uint32_t* a,
                                        const uint32_t* b) {
    asm volatile(
        "mma.sync.aligned.m16n8k16.row.col.f32.f16.f16.f32 "
        "{%0,%1,%2,%3}, {%4,%5,%6,%7}, {%8,%9}, {%0,%1,%2,%3};"
        : "+f"(d[0]), "+f"(d[1]), "+f"(d[2]), "+f"(d[3])
        : "r"(a[0]), "r"(a[1]), "r"(a[2]), "r"(a[3]), "r"(b[0]), "r"(b[1]));
}

__device__ __forceinline__ void ldsm_x4(uint32_t* r, uint32_t addr) {
    asm volatile("ldmatrix.sync.aligned.m8n8.x4.shared.b16 {%0,%1,%2,%3}, [%4];"
                 : "=r"(r[0]), "=r"(r[1]), "=r"(r[2]), "=r"(r[3]) : "r"(addr));
}

__device__ __forceinline__ void ldsm_x4_t(uint32_t* r, uint32_t addr) {
    asm volatile("ldmatrix.sync.aligned.m8n8.x4.trans.shared.b16 {%0,%1,%2,%3}, [%4];"
                 : "=r"(r[0]), "=r"(r[1]), "=r"(r[2]), "=r"(r[3]) : "r"(addr));
}

__device__ __forceinline__ float ex2f(float x) {
    float r;
    asm("ex2.approx.ftz.f32 %0, %1;" : "=f"(r) : "f"(x));
    return r;
}

__device__ __forceinline__ uint32_t ex2_pack(float hi, float lo) {
    uint32_t t, r;
    asm("cvt.rn.f16x2.f32 %0, %1, %2;" : "=r"(t) : "f"(hi), "f"(lo));
    asm("ex2.approx.f16x2 %0, %1;" : "=r"(r) : "r"(t));
    return r;
}

#define CP_ASYNC16(dst, src) \
    asm volatile("cp.async.cg.shared.global [%0], [%1], 16;" \
                 :: "r"(dst), "l"(src) : "memory")
#define CP_COMMIT() asm volatile("cp.async.commit_group;" ::: "memory")

// ---------------------------------------------------------------------------
// Prepass kernels
// ---------------------------------------------------------------------------
__global__ void to_f16(const float4* __restrict__ in, __half* __restrict__ out,
                       int n4)
{
    int i = blockIdx.x * blockDim.x + threadIdx.x;
    if (i >= n4) return;
    float4 v = in[i];
    __half2 a = __floats2half2_rn(v.x, v.y);
    __half2 b = __floats2half2_rn(v.z, v.w);
    uint2 w;
    w.x = *(uint32_t*)&a;
    w.y = *(uint32_t*)&b;
    *(uint2*)(out + (size_t)i * 4) = w;
}

// transpose K x C fp32 -> [C][K] f16
__global__ void transpose_f16(const float* __restrict__ in,
                              __half* __restrict__ outT, int Kdim, int Cdim)
{
    __shared__ float tile[32][33];
    int bx = blockIdx.x * 32;
    int by = blockIdx.y * 32;
    int x = threadIdx.x, y = threadIdx.y;   // 32 x 8
    #pragma unroll
    for (int j = 0; j < 4; ++j)
        tile[y + j * 8][x] = in[(size_t)(by + y + j * 8) * Cdim + bx + x];
    __syncthreads();
    #pragma unroll
    for (int j = 0; j < 4; ++j) {
        float v = tile[x][y + j * 8];
        outT[(size_t)(bx + y + j * 8) * Kdim + by + x] = __float2half(v);
    }
}

// ---------------------------------------------------------------------------
// Single-term f16 GEMM: C(MxN) = A(MxK) @ BT(NxK)^T + bias.
// 256x128 block tile, BK=64, 4-stage cp.async pipeline, 8 warps (4x2),
// warp tile 64x64. Smem row stride 72 halves (144B) -> conflict-free ldsm.
// MODE 0: fp32 out + bias.   MODE 1: f16 out + bias, xCSC on Q segment.
// ---------------------------------------------------------------------------
#define GSTAGES   4
#define GAPLANE_B 36864                  // 256 * 144
#define GSTAGE_B  55296                  // A (256 rows) + B (128 rows)
#define GEMM_SMEM (GSTAGES * GSTAGE_B)   // 221184

template<int MODE>
__global__ __launch_bounds__(256, 1) void gemm_f16(
    const __half* __restrict__ A, const __half* __restrict__ BT,
    const float* __restrict__ bias, float* __restrict__ C,
    __half* __restrict__ H, int N, int K)
{
    extern __shared__ __align__(16) char sm[];
    const uint32_t smb = smem_to_u32(sm);

    const int tid  = threadIdx.x;
    const int lane = tid & 31;
    const int warp = tid >> 5;
    const int wm   = warp >> 1;        // 0..3
    const int wn   = warp & 1;         // 0..1
    const int bm   = blockIdx.y * 256;
    const int bn   = blockIdx.x * 128;

    auto issue = [&](int t, int s) {
        const uint32_t dst = smb + s * GSTAGE_B;
        const size_t k0 = (size_t)t * 64;
        #pragma unroll
        for (int i = 0; i < 8; ++i) {
            int c = (i << 8) + tid;
            int r = c >> 3, ch = c & 7;
            uint32_t so = (uint32_t)(r * 144 + ch * 16);
            CP_ASYNC16(dst + so,
                       (const char*)(A + (size_t)(bm + r) * K + k0 + ch * 8));
        }
        #pragma unroll
        for (int i = 0; i < 4; ++i) {
            int c = (i << 8) + tid;
            int r = c >> 3, ch = c & 7;
            uint32_t so = (uint32_t)(r * 144 + ch * 16);
            CP_ASYNC16(dst + GAPLANE_B + so,
                       (const char*)(BT + (size_t)(bn + r) * K + k0 + ch * 8));
        }
    };

    float acc[4][8][4];
    #pragma unroll
    for (int i = 0; i < 4; ++i)
        #pragma unroll
        for (int j = 0; j < 8; ++j)
            #pragma unroll
            for (int k = 0; k < 4; ++k) acc[i][j][k] = 0.0f;

    const int nstage = K >> 6;   // 16

    #pragma unroll
    for (int ps = 0; ps < GSTAGES - 1; ++ps) {
        if (ps < nstage) issue(ps, ps);
        CP_COMMIT();
    }

    for (int t = 0; t < nstage; ++t) {
        asm volatile("cp.async.wait_group %0;" :: "n"(GSTAGES - 2) : "memory");
        __syncthreads();

        const uint32_t pA = smb + (t & (GSTAGES - 1)) * GSTAGE_B;
        const uint32_t pB = pA + GAPLANE_B;

        #pragma unroll
        for (int kc = 0; kc < 4; ++kc) {
            uint32_t b[4][4];
            #pragma unroll
            for (int pr = 0; pr < 4; ++pr) {
                uint32_t boff = (uint32_t)(wn * 64 + pr * 16
                              + ((lane >> 4) & 1) * 8 + (lane & 7)) * 144
                              + (uint32_t)(kc * 16 + ((lane >> 3) & 1) * 8) * 2;
                ldsm_x4(b[pr], pB + boff);
            }
            #pragma unroll
            for (int mt = 0; mt < 4; ++mt) {
                uint32_t aoff = (uint32_t)(wm * 64 + mt * 16 + (lane & 15)) * 144
                              + (uint32_t)(kc * 16 + ((lane >> 4) & 1) * 8) * 2;
                uint32_t a[4];
                ldsm_x4(a, pA + aoff);
                #pragma unroll
                for (int pr = 0; pr < 4; ++pr) {
                    mma_f16(acc[mt][2 * pr],     a, &b[pr][0]);
                    mma_f16(acc[mt][2 * pr + 1], a, &b[pr][2]);
                }
            }
        }

        if (t + GSTAGES - 1 < nstage)
            issue(t + GSTAGES - 1, (t + GSTAGES - 1) & (GSTAGES - 1));
        CP_COMMIT();
    }

    // epilogue
    const int g   = lane >> 2;
    const int tig = lane & 3;
    const float scale = (MODE == 1 && (bn >> 10) == 0) ? CSC : 1.0f;
    #pragma unroll
    for (int ntl = 0; ntl < 8; ++ntl) {
        int colg = bn + wn * 64 + ntl * 8 + tig * 2;
        float b0 = __ldg(bias + colg);
        float b1 = __ldg(bias + colg + 1);
        #pragma unroll
        for (int mt = 0; mt < 4; ++mt) {
            int row = bm + wm * 64 + mt * 16 + g;
            float v0 = acc[mt][ntl][0] + b0;
            float v1 = acc[mt][ntl][1] + b1;
            float v2 = acc[mt][ntl][2] + b0;
            float v3 = acc[mt][ntl][3] + b1;
            if (MODE == 0) {
                float2 o0, o1;
                o0.x = v0; o0.y = v1;
                o1.x = v2; o1.y = v3;
                *(float2*)&C[(size_t)row * N + colg]       = o0;
                *(float2*)&C[(size_t)(row + 8) * N + colg] = o1;
            } else {
                __half2 h0 = __floats2half2_rn(v0 * scale, v1 * scale);
                __half2 h1 = __floats2half2_rn(v2 * scale, v3 * scale);
                *(uint32_t*)(H + (size_t)row * N + colg)       = *(uint32_t*)&h0;
                *(uint32_t*)(H + (size_t)(row + 8) * N + colg) = *(uint32_t*)&h1;
            }
        }
    }
}

// ---------------------------------------------------------------------------
// Tensor-core flash attention (causal, log2-domain softmax), all-f16 operands.
// Block = (128 queries, head, batch), 8 warps x 16 query rows.
// KV tiles of 128 keys, cp.async double-buffered.
// Smem: Q 18432 | 2 x [K 18432 | V 18432] = 92160 bytes.
// ---------------------------------------------------------------------------
#define FL_STAGE 36864
#define FL_SMEM  (18432 + 2 * FL_STAGE)

__global__ __launch_bounds__(256, 1) void flash_mma(
    const __half* __restrict__ qkv, __half* __restrict__ Og)
{
    extern __shared__ __align__(16) char sm[];
    const uint32_t smb = smem_to_u32(sm);
    const uint32_t sQ  = smb;
    const uint32_t sKV = smb + 18432;

    const int tid  = threadIdx.x;
    const int lane = tid & 31;
    const int w    = tid >> 5;
    const int qt   = blockIdx.x;
    const int h    = blockIdx.y;
    const int b    = blockIdx.z;
    const int q0   = qt * 128;
    const size_t rowbase = (size_t)b * SS;
    const int colb = h * HD;

    auto issue_kv = [&](int kt, int s) {
        const uint32_t dst = sKV + s * FL_STAGE;
        const size_t krow0 = rowbase + (size_t)kt * 128;
        #pragma unroll
        for (int i = 0; i < 4; ++i) {
            int c = (i << 8) + tid;
            int r = c >> 3, ch = c & 7;
            size_t go = (krow0 + r) * (3 * NX) + colb + ch * 8;
            uint32_t so = (uint32_t)(r * 144 + ch * 16);
            CP_ASYNC16(dst + so,         (const char*)(qkv + NX + go));
            CP_ASYNC16(dst + 18432 + so, (const char*)(qkv + 2 * NX + go));
        }
    };

    issue_kv(0, 0);
    CP_COMMIT();

    // load Q tile into smem (f16, single plane)
    {
        int r  = tid >> 1;
        int d0 = (tid & 1) * 32;
        const __half* gq = qkv + (rowbase + q0 + r) * (3 * NX) + colb + d0;
        uint32_t so = (uint32_t)(r * 144 + d0 * 2);
        #pragma unroll
        for (int i = 0; i < 4; ++i)
            *(uint4*)(sm + so + i * 16) = *(const uint4*)(gq + i * 8);
    }

    float O[8][4];
    #pragma unroll
    for (int i = 0; i < 8; ++i)
        #pragma unroll
        for (int j = 0; j < 4; ++j) O[i][j] = 0.0f;
    float mprev_g = -1e30f, mprev_h = -1e30f;
    float lsum_g = 0.0f, lsum_h = 0.0f;

    const uint32_t ones[2] = {0x3C003C00u, 0x3C003C00u};

    for (int kt = 0; kt <= qt; ++kt) {
        if (kt < qt) {
            issue_kv(kt + 1, (kt + 1) & 1);
            CP_COMMIT();
            asm volatile("cp.async.wait_group 1;" ::: "memory");
        } else {
            asm volatile("cp.async.wait_group 0;" ::: "memory");
        }
        __syncthreads();

        const bool diag = (kt == qt);
        const int s = kt & 1;
        const uint32_t bK = sKV + s * FL_STAGE;
        const uint32_t bV = bK + 18432;
        const int nt_max = diag ? 2 * w + 2 : 16;
        const int kc_max = diag ? w + 1 : 8;

        // ---- S = Q K^T (single-term f16) ----
        float sc[16][4];
        #pragma unroll
        for (int i = 0; i < 16; ++i)
            #pragma unroll
            for (int j = 0; j < 4; ++j) sc[i][j] = 0.0f;

        #pragma unroll
        for (int kc = 0; kc < 4; ++kc) {
            uint32_t aoff = (uint32_t)(w * 16 + (lane & 15)) * 144
                          + (uint32_t)(kc * 16 + ((lane >> 4) & 1) * 8) * 2;
            uint32_t a[4];
            ldsm_x4(a, sQ + aoff);
            #pragma unroll
            for (int nt0 = 0; nt0 < 16; nt0 += 2) {
                if (nt0 < nt_max) {
                    uint32_t boff = (uint32_t)(nt0 * 8 + (lane & 7)
                                  + ((lane >> 4) & 1) * 8) * 144
                                  + (uint32_t)(kc * 16 + ((lane >> 3) & 1) * 8) * 2;
                    uint32_t bb[4];
                    ldsm_x4(bb, bK + boff);
                    mma_f16(sc[nt0],     a, &bb[0]);
                    mma_f16(sc[nt0 + 1], a, &bb[2]);
                }
            }
        }

        // ---- causal mask (diag tile) ----
        if (diag) {
            int rg = q0 + w * 16 + (lane >> 2);
            #pragma unroll
            for (int nt = 0; nt < 16; ++nt) {
                if (nt < nt_max) {
                    int cg = q0 + nt * 8 + (lane & 3) * 2;
                    if (cg     > rg)     sc[nt][0] = -1e30f;
                    if (cg + 1 > rg)     sc[nt][1] = -1e30f;
                    if (cg     > rg + 8) sc[nt][2] = -1e30f;
                    if (cg + 1 > rg + 8) sc[nt][3] = -1e30f;
                }
            }
        }

        // ---- online softmax (log2 domain) ----
        float mg = -1e30f, mh = -1e30f;
        #pragma unroll
        for (int nt = 0; nt < 16; ++nt) {
            if (nt < nt_max) {
                mg = fmaxf(mg, fmaxf(sc[nt][0], sc[nt][1]));
                mh = fmaxf(mh, fmaxf(sc[nt][2], sc[nt][3]));
            }
        }
        mg = fmaxf(mg, __shfl_xor_sync(0xffffffffu, mg, 1));
        mg = fmaxf(mg, __shfl_xor_sync(0xffffffffu, mg, 2));
        mh = fmaxf(mh, __shfl_xor_sync(0xffffffffu, mh, 1));
        mh = fmaxf(mh, __shfl_xor_sync(0xffffffffu, mh, 2));
        float mng = fmaxf(mprev_g, mg);
        float mnh = fmaxf(mprev_h, mh);
        float ag  = ex2f(mprev_g - mng);
        float ah2 = ex2f(mprev_h - mnh);
        mprev_g = mng; mprev_h = mnh;
        lsum_g *= ag; lsum_h *= ah2;
        #pragma unroll
        for (int dt = 0; dt < 8; ++dt) {
            O[dt][0] *= ag;  O[dt][1] *= ag;
            O[dt][2] *= ah2; O[dt][3] *= ah2;
        }

        // ---- P = 2^(S - m) packed half2 (A-fragment format) ----
        uint32_t p[16][2];
        #pragma unroll
        for (int nt = 0; nt < 16; ++nt) {
            if (nt < nt_max) {
                p[nt][0] = ex2_pack(sc[nt][1] - mng, sc[nt][0] - mng);
                p[nt][1] = ex2_pack(sc[nt][3] - mnh, sc[nt][2] - mnh);
            }
        }

        // ---- O += P V ; lsum += P @ ones ----
        float ssum[4] = {0.0f, 0.0f, 0.0f, 0.0f};
        #pragma unroll
        for (int kc2 = 0; kc2 < 8; ++kc2) {
            if (kc2 < kc_max) {
                uint32_t a[4] = { p[2 * kc2][0], p[2 * kc2][1],
                                  p[2 * kc2 + 1][0], p[2 * kc2 + 1][1] };
                mma_f16(ssum, a, ones);
                #pragma unroll
                for (int dt0 = 0; dt0 < 8; dt0 += 2) {
                    uint32_t voff = (uint32_t)(kc2 * 16 + (lane & 7)
                                  + ((lane >> 3) & 1) * 8) * 144
                                  + (uint32_t)(dt0 * 8 + ((lane >> 4) & 1) * 8) * 2;
                    uint32_t v4[4];
                    ldsm_x4_t(v4, bV + voff);
                    mma_f16(O[dt0],     a, &v4[0]);
                    mma_f16(O[dt0 + 1], a, &v4[2]);
                }
            }
        }
        lsum_g += ssum[0];
        lsum_h += ssum[2];

        __syncthreads();
    }

    // ---- epilogue: normalize, f16 store (merged heads) ----
    float ig = 1.0f / lsum_g;
    float ih = 1.0f / lsum_h;
    int r0 = q0 + w * 16 + (lane >> 2);
    size_t base0 = (rowbase + r0) * NX + colb + (lane & 3) * 2;
    size_t base1 = base0 + (size_t)8 * NX;
    #pragma unroll
    for (int dt = 0; dt < 8; ++dt) {
        __half2 o0 = __floats2half2_rn(O[dt][0] * ig, O[dt][1] * ig);
        __half2 o1 = __floats2half2_rn(O[dt][2] * ih, O[dt][3] * ih);
        *(uint32_t*)(Og + base0 + dt * 8) = *(uint32_t*)&o0;
        *(uint32_t*)(Og + base1 + dt * 8) = *(uint32_t*)&o1;
    }
}

// ---------------------------------------------------------------------------
extern "C" void kernel_launch(void* const* d_in, const int* in_sizes, int n_in,
                              void* d_out, int out_size)
{
    const float* x      = (const float*)d_in[0];
    const float* w_attn = (const float*)d_in[1];
    const float* b_attn = (const float*)d_in[2];
    const float* w_proj = (const float*)d_in[3];
    const float* b_proj = (const float*)d_in[4];
    float* out = (float*)d_out;

    __half *xh, *wat, *wpt, *qkvh, *oh;
    cudaGetSymbolAddress((void**)&xh,   g_xh);
    cudaGetSymbolAddress((void**)&wat,  g_wat);
    cudaGetSymbolAddress((void**)&wpt,  g_wpt);
    cudaGetSymbolAddress((void**)&qkvh, g_qkvh);
    cudaGetSymbolAddress((void**)&oh,   g_oh);

    // prepass
    {
        int n4 = BB * SS * NX / 4;
        to_f16<<<(n4 + 255) / 256, 256>>>((const float4*)x, xh, n4);
        transpose_f16<<<dim3(3 * NX / 32, NX / 32), dim3(32, 8)>>>(
            w_attn, wat, NX, 3 * NX);
        transpose_f16<<<dim3(NX / 32, NX / 32), dim3(32, 8)>>>(
            w_proj, wpt, NX, NX);
    }

    cudaFuncSetAttribute(gemm_f16<0>, cudaFuncAttributeMaxDynamicSharedMemorySize,
                         GEMM_SMEM);
    cudaFuncSetAttribute(gemm_f16<1>, cudaFuncAttributeMaxDynamicSharedMemorySize,
                         GEMM_SMEM);
    cudaFuncSetAttribute(flash_mma, cudaFuncAttributeMaxDynamicSharedMemorySize,
                         FL_SMEM);

    // 1) QKV projection -> f16 qkv (Q pre-scaled by CSC)
    {
        dim3 grid(3 * NX / 128, BB * SS / 256);   // 24 x 32
        gemm_f16<1><<<grid, 256, GEMM_SMEM>>>(
            xh, wat, b_attn, nullptr, qkvh, 3 * NX, NX);
    }

    // 2) flash attention -> f16 merged heads
    {
        dim3 grid(SS / 128, NH, BB);
        flash_mma<<<grid, 256, FL_SMEM>>>(qkvh, oh);
    }

    // 3) out = O @ w_proj + b_proj (fp32 out)
    {
        dim3 grid(NX / 128, BB * SS / 256);       // 8 x 32
        gemm_f16<0><<<grid, 256, GEMM_SMEM>>>(
            oh, wpt, b_proj, out, nullptr, NX, NX);
    }
}

// round 7
// speedup vs baseline: 6.2704x; 1.0133x over previous
#include <cuda_runtime.h>
#include <cuda_bf16.h>
#include <cuda_fp16.h>
#include <cstdint>

// Problem constants
#define BB 8
#define SS 1024
#define NX 1024
#define NH 16
#define HD 64

// log2(e) / sqrt(64) folded into Q
#define CSC 0.18033688011112042592f

// ---------------------------------------------------------------------------
// Scratch (device globals; allocation-free rule)
// ---------------------------------------------------------------------------
__device__ __half g_xh[(size_t)BB * SS * NX];           // x in f16
__device__ __half g_wat[(size_t)3 * NX * NX];           // w_attn^T [3NX][NX] f16
__device__ __half g_wpt[(size_t)NX * NX];               // w_proj^T [NX][NX] f16
__device__ __half g_qkvh[(size_t)BB * SS * 3 * NX];     // QKV (Q pre-scaled) f16
__device__ __half g_oh[(size_t)BB * SS * NX];           // attention out f16

__device__ __forceinline__ uint32_t smem_to_u32(const void* p) {
    uint32_t a;
    asm("{ .reg .u64 t; cvta.to.shared.u64 t, %1; cvt.u32.u64 %0, t; }"
        : "=r"(a) : "l"(p));
    return a;
}

// ---------------------------------------------------------------------------
// MMA / ldmatrix / misc helpers
// ---------------------------------------------------------------------------
__device__ __forceinline__ void mma_f16(float* d, const uint32_t* a,
                                        const uint32_t* b) {
    asm volatile(
        "mma.sync.aligned.m16n8k16.row.col.f32.f16.f16.f32 "
        "{%0,%1,%2,%3}, {%4,%5,%6,%7}, {%8,%9}, {%0,%1,%2,%3};"
        : "+f"(d[0]), "+f"(d[1]), "+f"(d[2]), "+f"(d[3])
        : "r"(a[0]), "r"(a[1]), "r"(a[2]), "r"(a[3]), "r"(b[0]), "r"(b[1]));
}

__device__ __forceinline__ void ldsm_x4(uint32_t* r, uint32_t addr) {
    asm volatile("ldmatrix.sync.aligned.m8n8.x4.shared.b16 {%0,%1,%2,%3}, [%4];"
                 : "=r"(r[0]), "=r"(r[1]), "=r"(r[2]), "=r"(r[3]) : "r"(addr));
}

__device__ __forceinline__ void ldsm_x4_t(uint32_t* r, uint32_t addr) {
    asm volatile("ldmatrix.sync.aligned.m8n8.x4.trans.shared.b16 {%0,%1,%2,%3}, [%4];"
                 : "=r"(r[0]), "=r"(r[1]), "=r"(r[2]), "=r"(r[3]) : "r"(addr));
}

__device__ __forceinline__ float ex2f(float x) {
    float r;
    asm("ex2.approx.ftz.f32 %0, %1;" : "=f"(r) : "f"(x));
    return r;
}

__device__ __forceinline__ uint32_t ex2_pack(float hi, float lo) {
    uint32_t t, r;
    asm("cvt.rn.f16x2.f32 %0, %1, %2;" : "=r"(t) : "f"(hi), "f"(lo));
    asm("ex2.approx.f16x2 %0, %1;" : "=r"(r) : "r"(t));
    return r;
}

#define CP_ASYNC16(dst, src) \
    asm volatile("cp.async.cg.shared.global [%0], [%1], 16;" \
                 :: "r"(dst), "l"(src) : "memory")
#define CP_COMMIT() asm volatile("cp.async.commit_group;" ::: "memory")

// ---------------------------------------------------------------------------
// Prepass kernels
// ---------------------------------------------------------------------------
__global__ void to_f16(const float4* __restrict__ in, __half* __restrict__ out,
                       int n4)
{
    int i = blockIdx.x * blockDim.x + threadIdx.x;
    if (i >= n4) return;
    float4 v = in[i];
    __half2 a = __floats2half2_rn(v.x, v.y);
    __half2 b = __floats2half2_rn(v.z, v.w);
    uint2 w;
    w.x = *(uint32_t*)&a;
    w.y = *(uint32_t*)&b;
    *(uint2*)(out + (size_t)i * 4) = w;
}

// transpose K x C fp32 -> [C][K] f16
__global__ void transpose_f16(const float* __restrict__ in,
                              __half* __restrict__ outT, int Kdim, int Cdim)
{
    __shared__ float tile[32][33];
    int bx = blockIdx.x * 32;
    int by = blockIdx.y * 32;
    int x = threadIdx.x, y = threadIdx.y;   // 32 x 8
    #pragma unroll
    for (int j = 0; j < 4; ++j)
        tile[y + j * 8][x] = in[(size_t)(by + y + j * 8) * Cdim + bx + x];
    __syncthreads();
    #pragma unroll
    for (int j = 0; j < 4; ++j) {
        float v = tile[x][y + j * 8];
        outT[(size_t)(bx + y + j * 8) * Kdim + by + x] = __float2half(v);
    }
}

// ---------------------------------------------------------------------------
// Single-term f16 GEMM: C(MxN) = A(MxK) @ BT(NxK)^T + bias.
// 256x128 block tile, BK=64, 4-stage cp.async pipeline, 16 warps (4x4),
// warp tile 64x32 -> 4 warps per SMSP for latency hiding.
// Smem row stride 72 halves (144B) -> conflict-free ldsm.
// MODE 0: fp32 out + bias.   MODE 1: f16 out + bias, xCSC on Q segment.
// ---------------------------------------------------------------------------
#define GSTAGES   4
#define GAPLANE_B 36864                  // 256 * 144
#define GSTAGE_B  55296                  // A (256 rows) + B (128 rows)
#define GEMM_SMEM (GSTAGES * GSTAGE_B)   // 221184

template<int MODE>
__global__ __launch_bounds__(512, 1) void gemm_f16(
    const __half* __restrict__ A, const __half* __restrict__ BT,
    const float* __restrict__ bias, float* __restrict__ C,
    __half* __restrict__ H, int N, int K)
{
    extern __shared__ __align__(16) char sm[];
    const uint32_t smb = smem_to_u32(sm);

    const int tid  = threadIdx.x;
    const int lane = tid & 31;
    const int warp = tid >> 5;
    const int wm   = warp >> 2;        // 0..3
    const int wn   = warp & 3;         // 0..3
    const int bm   = blockIdx.y * 256;
    const int bn   = blockIdx.x * 128;

    auto issue = [&](int t, int s) {
        const uint32_t dst = smb + s * GSTAGE_B;
        const size_t k0 = (size_t)t * 64;
        #pragma unroll
        for (int i = 0; i < 4; ++i) {
            int c = (i << 9) + tid;
            int r = c >> 3, ch = c & 7;
            uint32_t so = (uint32_t)(r * 144 + ch * 16);
            CP_ASYNC16(dst + so,
                       (const char*)(A + (size_t)(bm + r) * K + k0 + ch * 8));
        }
        #pragma unroll
        for (int i = 0; i < 2; ++i) {
            int c = (i << 9) + tid;
            int r = c >> 3, ch = c & 7;
            uint32_t so = (uint32_t)(r * 144 + ch * 16);
            CP_ASYNC16(dst + GAPLANE_B + so,
                       (const char*)(BT + (size_t)(bn + r) * K + k0 + ch * 8));
        }
    };

    float acc[4][4][4];
    #pragma unroll
    for (int i = 0; i < 4; ++i)
        #pragma unroll
        for (int j = 0; j < 4; ++j)
            #pragma unroll
            for (int k = 0; k < 4; ++k) acc[i][j][k] = 0.0f;

    const int nstage = K >> 6;   // 16

    #pragma unroll
    for (int ps = 0; ps < GSTAGES - 1; ++ps) {
        if (ps < nstage) issue(ps, ps);
        CP_COMMIT();
    }

    for (int t = 0; t < nstage; ++t) {
        asm volatile("cp.async.wait_group %0;" :: "n"(GSTAGES - 2) : "memory");
        __syncthreads();

        const uint32_t pA = smb + (t & (GSTAGES - 1)) * GSTAGE_B;
        const uint32_t pB = pA + GAPLANE_B;

        #pragma unroll
        for (int kc = 0; kc < 4; ++kc) {
            uint32_t b[2][4];
            #pragma unroll
            for (int pr = 0; pr < 2; ++pr) {
                uint32_t boff = (uint32_t)(wn * 32 + pr * 16
                              + ((lane >> 4) & 1) * 8 + (lane & 7)) * 144
                              + (uint32_t)(kc * 16 + ((lane >> 3) & 1) * 8) * 2;
                ldsm_x4(b[pr], pB + boff);
            }
            #pragma unroll
            for (int mt = 0; mt < 4; ++mt) {
                uint32_t aoff = (uint32_t)(wm * 64 + mt * 16 + (lane & 15)) * 144
                              + (uint32_t)(kc * 16 + ((lane >> 4) & 1) * 8) * 2;
                uint32_t a[4];
                ldsm_x4(a, pA + aoff);
                mma_f16(acc[mt][0], a, &b[0][0]);
                mma_f16(acc[mt][1], a, &b[0][2]);
                mma_f16(acc[mt][2], a, &b[1][0]);
                mma_f16(acc[mt][3], a, &b[1][2]);
            }
        }

        if (t + GSTAGES - 1 < nstage)
            issue(t + GSTAGES - 1, (t + GSTAGES - 1) & (GSTAGES - 1));
        CP_COMMIT();
    }

    // epilogue
    const int g   = lane >> 2;
    const int tig = lane & 3;
    const float scale = (MODE == 1 && (bn >> 10) == 0) ? CSC : 1.0f;
    #pragma unroll
    for (int ntl = 0; ntl < 4; ++ntl) {
        int colg = bn + wn * 32 + ntl * 8 + tig * 2;
        float b0 = __ldg(bias + colg);
        float b1 = __ldg(bias + colg + 1);
        #pragma unroll
        for (int mt = 0; mt < 4; ++mt) {
            int row = bm + wm * 64 + mt * 16 + g;
            float v0 = acc[mt][ntl][0] + b0;
            float v1 = acc[mt][ntl][1] + b1;
            float v2 = acc[mt][ntl][2] + b0;
            float v3 = acc[mt][ntl][3] + b1;
            if (MODE == 0) {
                float2 o0, o1;
                o0.x = v0; o0.y = v1;
                o1.x = v2; o1.y = v3;
                *(float2*)&C[(size_t)row * N + colg]       = o0;
                *(float2*)&C[(size_t)(row + 8) * N + colg] = o1;
            } else {
                __half2 h0 = __floats2half2_rn(v0 * scale, v1 * scale);
                __half2 h1 = __floats2half2_rn(v2 * scale, v3 * scale);
                *(uint32_t*)(H + (size_t)row * N + colg)       = *(uint32_t*)&h0;
                *(uint32_t*)(H + (size_t)(row + 8) * N + colg) = *(uint32_t*)&h1;
            }
        }
    }
}

// ---------------------------------------------------------------------------
// Tensor-core flash attention (causal, log2-domain softmax), all-f16 operands.
// Block = (128 queries, head, batch), 8 warps x 16 query rows.
// KV tiles of 128 keys, cp.async double-buffered.
// Smem: Q 18432 | 2 x [K 18432 | V 18432] = 92160 bytes.
// ---------------------------------------------------------------------------
#define FL_STAGE 36864
#define FL_SMEM  (18432 + 2 * FL_STAGE)

__global__ __launch_bounds__(256, 1) void flash_mma(
    const __half* __restrict__ qkv, __half* __restrict__ Og)
{
    extern __shared__ __align__(16) char sm[];
    const uint32_t smb = smem_to_u32(sm);
    const uint32_t sQ  = smb;
    const uint32_t sKV = smb + 18432;

    const int tid  = threadIdx.x;
    const int lane = tid & 31;
    const int w    = tid >> 5;
    const int qt   = blockIdx.x;
    const int h    = blockIdx.y;
    const int b    = blockIdx.z;
    const int q0   = qt * 128;
    const size_t rowbase = (size_t)b * SS;
    const int colb = h * HD;

    auto issue_kv = [&](int kt, int s) {
        const uint32_t dst = sKV + s * FL_STAGE;
        const size_t krow0 = rowbase + (size_t)kt * 128;
        #pragma unroll
        for (int i = 0; i < 4; ++i) {
            int c = (i << 8) + tid;
            int r = c >> 3, ch = c & 7;
            size_t go = (krow0 + r) * (3 * NX) + colb + ch * 8;
            uint32_t so = (uint32_t)(r * 144 + ch * 16);
            CP_ASYNC16(dst + so,         (const char*)(qkv + NX + go));
            CP_ASYNC16(dst + 18432 + so, (const char*)(qkv + 2 * NX + go));
        }
    };

    issue_kv(0, 0);
    CP_COMMIT();

    // load Q tile into smem (f16, single plane)
    {
        int r  = tid >> 1;
        int d0 = (tid & 1) * 32;
        const __half* gq = qkv + (rowbase + q0 + r) * (3 * NX) + colb + d0;
        uint32_t so = (uint32_t)(r * 144 + d0 * 2);
        #pragma unroll
        for (int i = 0; i < 4; ++i)
            *(uint4*)(sm + so + i * 16) = *(const uint4*)(gq + i * 8);
    }

    float O[8][4];
    #pragma unroll
    for (int i = 0; i < 8; ++i)
        #pragma unroll
        for (int j = 0; j < 4; ++j) O[i][j] = 0.0f;
    float mprev_g = -1e30f, mprev_h = -1e30f;
    float lsum_g = 0.0f, lsum_h = 0.0f;

    const uint32_t ones[2] = {0x3C003C00u, 0x3C003C00u};

    for (int kt = 0; kt <= qt; ++kt) {
        if (kt < qt) {
            issue_kv(kt + 1, (kt + 1) & 1);
            CP_COMMIT();
            asm volatile("cp.async.wait_group 1;" ::: "memory");
        } else {
            asm volatile("cp.async.wait_group 0;" ::: "memory");
        }
        __syncthreads();

        const bool diag = (kt == qt);
        const int s = kt & 1;
        const uint32_t bK = sKV + s * FL_STAGE;
        const uint32_t bV = bK + 18432;
        const int nt_max = diag ? 2 * w + 2 : 16;
        const int kc_max = diag ? w + 1 : 8;

        // ---- S = Q K^T (single-term f16) ----
        float sc[16][4];
        #pragma unroll
        for (int i = 0; i < 16; ++i)
            #pragma unroll
            for (int j = 0; j < 4; ++j) sc[i][j] = 0.0f;

        #pragma unroll
        for (int kc = 0; kc < 4; ++kc) {
            uint32_t aoff = (uint32_t)(w * 16 + (lane & 15)) * 144
                          + (uint32_t)(kc * 16 + ((lane >> 4) & 1) * 8) * 2;
            uint32_t a[4];
            ldsm_x4(a, sQ + aoff);
            #pragma unroll
            for (int nt0 = 0; nt0 < 16; nt0 += 2) {
                if (nt0 < nt_max) {
                    uint32_t boff = (uint32_t)(nt0 * 8 + (lane & 7)
                                  + ((lane >> 4) & 1) * 8) * 144
                                  + (uint32_t)(kc * 16 + ((lane >> 3) & 1) * 8) * 2;
                    uint32_t bb[4];
                    ldsm_x4(bb, bK + boff);
                    mma_f16(sc[nt0],     a, &bb[0]);
                    mma_f16(sc[nt0 + 1], a, &bb[2]);
                }
            }
        }

        // ---- causal mask (diag tile) ----
        if (diag) {
            int rg = q0 + w * 16 + (lane >> 2);
            #pragma unroll
            for (int nt = 0; nt < 16; ++nt) {
                if (nt < nt_max) {
                    int cg = q0 + nt * 8 + (lane & 3) * 2;
                    if (cg     > rg)     sc[nt][0] = -1e30f;
                    if (cg + 1 > rg)     sc[nt][1] = -1e30f;
                    if (cg     > rg + 8) sc[nt][2] = -1e30f;
                    if (cg + 1 > rg + 8) sc[nt][3] = -1e30f;
                }
            }
        }

        // ---- online softmax (log2 domain) ----
        float mg = -1e30f, mh = -1e30f;
        #pragma unroll
        for (int nt = 0; nt < 16; ++nt) {
            if (nt < nt_max) {
                mg = fmaxf(mg, fmaxf(sc[nt][0], sc[nt][1]));
                mh = fmaxf(mh, fmaxf(sc[nt][2], sc[nt][3]));
            }
        }
        mg = fmaxf(mg, __shfl_xor_sync(0xffffffffu, mg, 1));
        mg = fmaxf(mg, __shfl_xor_sync(0xffffffffu, mg, 2));
        mh = fmaxf(mh, __shfl_xor_sync(0xffffffffu, mh, 1));
        mh = fmaxf(mh, __shfl_xor_sync(0xffffffffu, mh, 2));
        float mng = fmaxf(mprev_g, mg);
        float mnh = fmaxf(mprev_h, mh);
        float ag  = ex2f(mprev_g - mng);
        float ah2 = ex2f(mprev_h - mnh);
        mprev_g = mng; mprev_h = mnh;
        lsum_g *= ag; lsum_h *= ah2;
        #pragma unroll
        for (int dt = 0; dt < 8; ++dt) {
            O[dt][0] *= ag;  O[dt][1] *= ag;
            O[dt][2] *= ah2; O[dt][3] *= ah2;
        }

        // ---- P = 2^(S - m) packed half2 (A-fragment format) ----
        uint32_t p[16][2];
        #pragma unroll
        for (int nt = 0; nt < 16; ++nt) {
            if (nt < nt_max) {
                p[nt][0] = ex2_pack(sc[nt][1] - mng, sc[nt][0] - mng);
                p[nt][1] = ex2_pack(sc[nt][3] - mnh, sc[nt][2] - mnh);
            }
        }

        // ---- O += P V ; lsum += P @ ones ----
        float ssum[4] = {0.0f, 0.0f, 0.0f, 0.0f};
        #pragma unroll
        for (int kc2 = 0; kc2 < 8; ++kc2) {
            if (kc2 < kc_max) {
                uint32_t a[4] = { p[2 * kc2][0], p[2 * kc2][1],
                                  p[2 * kc2 + 1][0], p[2 * kc2 + 1][1] };
                mma_f16(ssum, a, ones);
                #pragma unroll
                for (int dt0 = 0; dt0 < 8; dt0 += 2) {
                    uint32_t voff = (uint32_t)(kc2 * 16 + (lane & 7)
                                  + ((lane >> 3) & 1) * 8) * 144
                                  + (uint32_t)(dt0 * 8 + ((lane >> 4) & 1) * 8) * 2;
                    uint32_t v4[4];
                    ldsm_x4_t(v4, bV + voff);
                    mma_f16(O[dt0],     a, &v4[0]);
                    mma_f16(O[dt0 + 1], a, &v4[2]);
                }
            }
        }
        lsum_g += ssum[0];
        lsum_h += ssum[2];

        __syncthreads();
    }

    // ---- epilogue: normalize, f16 store (merged heads) ----
    float ig = 1.0f / lsum_g;
    float ih = 1.0f / lsum_h;
    int r0 = q0 + w * 16 + (lane >> 2);
    size_t base0 = (rowbase + r0) * NX + colb + (lane & 3) * 2;
    size_t base1 = base0 + (size_t)8 * NX;
    #pragma unroll
    for (int dt = 0; dt < 8; ++dt) {
        __half2 o0 = __floats2half2_rn(O[dt][0] * ig, O[dt][1] * ig);
        __half2 o1 = __floats2half2_rn(O[dt][2] * ih, O[dt][3] * ih);
        *(uint32_t*)(Og + base0 + dt * 8) = *(uint32_t*)&o0;
        *(uint32_t*)(Og + base1 + dt * 8) = *(uint32_t*)&o1;
    }
}

// ---------------------------------------------------------------------------
extern "C" void kernel_launch(void* const* d_in, const int* in_sizes, int n_in,
                              void* d_out, int out_size)
{
    const float* x      = (const float*)d_in[0];
    const float* w_attn = (const float*)d_in[1];
    const float* b_attn = (const float*)d_in[2];
    const float* w_proj = (const float*)d_in[3];
    const float* b_proj = (const float*)d_in[4];
    float* out = (float*)d_out;

    __half *xh, *wat, *wpt, *qkvh, *oh;
    cudaGetSymbolAddress((void**)&xh,   g_xh);
    cudaGetSymbolAddress((void**)&wat,  g_wat);
    cudaGetSymbolAddress((void**)&wpt,  g_wpt);
    cudaGetSymbolAddress((void**)&qkvh, g_qkvh);
    cudaGetSymbolAddress((void**)&oh,   g_oh);

    // prepass
    {
        int n4 = BB * SS * NX / 4;
        to_f16<<<(n4 + 255) / 256, 256>>>((const float4*)x, xh, n4);
        transpose_f16<<<dim3(3 * NX / 32, NX / 32), dim3(32, 8)>>>(
            w_attn, wat, NX, 3 * NX);
        transpose_f16<<<dim3(NX / 32, NX / 32), dim3(32, 8)>>>(
            w_proj, wpt, NX, NX);
    }

    cudaFuncSetAttribute(gemm_f16<0>, cudaFuncAttributeMaxDynamicSharedMemorySize,
                         GEMM_SMEM);
    cudaFuncSetAttribute(gemm_f16<1>, cudaFuncAttributeMaxDynamicSharedMemorySize,
                         GEMM_SMEM);
    cudaFuncSetAttribute(flash_mma, cudaFuncAttributeMaxDynamicSharedMemorySize,
                         FL_SMEM);

    // 1) QKV projection -> f16 qkv (Q pre-scaled by CSC)
    {
        dim3 grid(3 * NX / 128, BB * SS / 256);   // 24 x 32
        gemm_f16<1><<<grid, 512, GEMM_SMEM>>>(
            xh, wat, b_attn, nullptr, qkvh, 3 * NX, NX);
    }

    // 2) flash attention -> f16 merged heads
    {
        dim3 grid(SS / 128, NH, BB);
        flash_mma<<<grid, 256, FL_SMEM>>>(qkvh, oh);
    }

    // 3) out = O @ w_proj + b_proj (fp32 out)
    {
        dim3 grid(NX / 128, BB * SS / 256);       // 8 x 32
        gemm_f16<0><<<grid, 512, GEMM_SMEM>>>(
            oh, wpt, b_proj, out, nullptr, NX, NX);
    }
}

// round 8
// speedup vs baseline: 6.6996x; 1.0684x over previous
#include <cuda_runtime.h>
#include <cuda_bf16.h>
#include <cuda_fp16.h>
#include <cstdint>

// Problem constants
#define BB 8
#define SS 1024
#define NX 1024
#define NH 16
#define HD 64

// log2(e) / sqrt(64) folded into Q
#define CSC 0.18033688011112042592f

// ---------------------------------------------------------------------------
// Scratch (device globals; allocation-free rule)
// ---------------------------------------------------------------------------
__device__ __half g_xh[(size_t)BB * SS * NX];           // x in f16
__device__ __half g_wat[(size_t)3 * NX * NX];           // w_attn^T [3NX][NX] f16
__device__ __half g_wpt[(size_t)NX * NX];               // w_proj^T [NX][NX] f16
__device__ __half g_qkvh[(size_t)BB * SS * 3 * NX];     // QKV (Q pre-scaled) f16
__device__ __half g_oh[(size_t)BB * SS * NX];           // attention out f16

__device__ __forceinline__ uint32_t smem_to_u32(const void* p) {
    uint32_t a;
    asm("{ .reg .u64 t; cvta.to.shared.u64 t, %1; cvt.u32.u64 %0, t; }"
        : "=r"(a) : "l"(p));
    return a;
}

// ---------------------------------------------------------------------------
// MMA / ldmatrix / misc helpers
// ---------------------------------------------------------------------------
__device__ __forceinline__ void mma_f16(float* d, const uint32_t* a,
                                        const uint32_t* b) {
    asm volatile(
        "mma.sync.aligned.m16n8k16.row.col.f32.f16.f16.f32 "
        "{%0,%1,%2,%3}, {%4,%5,%6,%7}, {%8,%9}, {%0,%1,%2,%3};"
        : "+f"(d[0]), "+f"(d[1]), "+f"(d[2]), "+f"(d[3])
        : "r"(a[0]), "r"(a[1]), "r"(a[2]), "r"(a[3]), "r"(b[0]), "r"(b[1]));
}

__device__ __forceinline__ void ldsm_x4(uint32_t* r, uint32_t addr) {
    asm volatile("ldmatrix.sync.aligned.m8n8.x4.shared.b16 {%0,%1,%2,%3}, [%4];"
                 : "=r"(r[0]), "=r"(r[1]), "=r"(r[2]), "=r"(r[3]) : "r"(addr));
}

__device__ __forceinline__ void ldsm_x4_t(uint32_t* r, uint32_t addr) {
    asm volatile("ldmatrix.sync.aligned.m8n8.x4.trans.shared.b16 {%0,%1,%2,%3}, [%4];"
                 : "=r"(r[0]), "=r"(r[1]), "=r"(r[2]), "=r"(r[3]) : "r"(addr));
}

__device__ __forceinline__ float ex2f(float x) {
    float r;
    asm("ex2.approx.ftz.f32 %0, %1;" : "=f"(r) : "f"(x));
    return r;
}

__device__ __forceinline__ uint32_t ex2_pack(float hi, float lo) {
    uint32_t t, r;
    asm("cvt.rn.f16x2.f32 %0, %1, %2;" : "=r"(t) : "f"(hi), "f"(lo));
    asm("ex2.approx.f16x2 %0, %1;" : "=r"(r) : "r"(t));
    return r;
}

#define CP_ASYNC16(dst, src) \
    asm volatile("cp.async.cg.shared.global [%0], [%1], 16;" \
                 :: "r"(dst), "l"(src) : "memory")
#define CP_COMMIT() asm volatile("cp.async.commit_group;" ::: "memory")

// ---------------------------------------------------------------------------
// Prepass kernels
// ---------------------------------------------------------------------------
__global__ void to_f16(const float4* __restrict__ in, __half* __restrict__ out,
                       int n4)
{
    int i = blockIdx.x * blockDim.x + threadIdx.x;
    if (i >= n4) return;
    float4 v = in[i];
    __half2 a = __floats2half2_rn(v.x, v.y);
    __half2 b = __floats2half2_rn(v.z, v.w);
    uint2 w;
    w.x = *(uint32_t*)&a;
    w.y = *(uint32_t*)&b;
    *(uint2*)(out + (size_t)i * 4) = w;
}

// transpose K x C fp32 -> [C][K] f16
__global__ void transpose_f16(const float* __restrict__ in,
                              __half* __restrict__ outT, int Kdim, int Cdim)
{
    __shared__ float tile[32][33];
    int bx = blockIdx.x * 32;
    int by = blockIdx.y * 32;
    int x = threadIdx.x, y = threadIdx.y;   // 32 x 8
    #pragma unroll
    for (int j = 0; j < 4; ++j)
        tile[y + j * 8][x] = in[(size_t)(by + y + j * 8) * Cdim + bx + x];
    __syncthreads();
    #pragma unroll
    for (int j = 0; j < 4; ++j) {
        float v = tile[x][y + j * 8];
        outT[(size_t)(bx + y + j * 8) * Kdim + by + x] = __float2half(v);
    }
}

// ---------------------------------------------------------------------------
// Single-term f16 GEMM: C(MxN) = A(MxK) @ BT(NxK)^T + bias.
// 128x128 block tile, BK=64, 3-stage cp.async pipeline, 8 warps (2x4),
// warp tile 64x32, 2 CTAs per SM (cross-CTA latency hiding).
// Smem row stride 72 halves (144B) -> conflict-free ldsm.
// MODE 0: fp32 out + bias.   MODE 1: f16 out + bias, xCSC on Q segment.
// ---------------------------------------------------------------------------
#define GSTAGES   3
#define GPLANE_B  18432                  // 128 * 144
#define GSTAGE_B  36864                  // A + B planes
#define GEMM_SMEM (GSTAGES * GSTAGE_B)   // 110592 -> 2 CTAs/SM

template<int MODE>
__global__ __launch_bounds__(256, 2) void gemm_f16(
    const __half* __restrict__ A, const __half* __restrict__ BT,
    const float* __restrict__ bias, float* __restrict__ C,
    __half* __restrict__ H, int N, int K)
{
    extern __shared__ __align__(16) char sm[];
    const uint32_t smb = smem_to_u32(sm);

    const int tid  = threadIdx.x;
    const int lane = tid & 31;
    const int warp = tid >> 5;
    const int wm   = warp >> 2;        // 0..1
    const int wn   = warp & 3;         // 0..3
    const int bm   = blockIdx.y * 128;
    const int bn   = blockIdx.x * 128;

    auto issue = [&](int t, int s) {
        const uint32_t dst = smb + s * GSTAGE_B;
        const size_t k0 = (size_t)t * 64;
        #pragma unroll
        for (int i = 0; i < 4; ++i) {
            int c = (i << 8) + tid;
            int r = c >> 3, ch = c & 7;
            uint32_t so = (uint32_t)(r * 144 + ch * 16);
            CP_ASYNC16(dst + so,
                       (const char*)(A + (size_t)(bm + r) * K + k0 + ch * 8));
            CP_ASYNC16(dst + GPLANE_B + so,
                       (const char*)(BT + (size_t)(bn + r) * K + k0 + ch * 8));
        }
    };

    float acc[4][4][4];
    #pragma unroll
    for (int i = 0; i < 4; ++i)
        #pragma unroll
        for (int j = 0; j < 4; ++j)
            #pragma unroll
            for (int k = 0; k < 4; ++k) acc[i][j][k] = 0.0f;

    const int nstage = K >> 6;   // 16

    issue(0, 0);
    CP_COMMIT();
    issue(1, 1);
    CP_COMMIT();

    for (int t = 0; t < nstage; ++t) {
        asm volatile("cp.async.wait_group 1;" ::: "memory");
        __syncthreads();

        const int slot = t % 3;
        const uint32_t pA = smb + slot * GSTAGE_B;
        const uint32_t pB = pA + GPLANE_B;

        #pragma unroll
        for (int kc = 0; kc < 4; ++kc) {
            uint32_t b[2][4];
            #pragma unroll
            for (int pr = 0; pr < 2; ++pr) {
                uint32_t boff = (uint32_t)(wn * 32 + pr * 16
                              + ((lane >> 4) & 1) * 8 + (lane & 7)) * 144
                              + (uint32_t)(kc * 16 + ((lane >> 3) & 1) * 8) * 2;
                ldsm_x4(b[pr], pB + boff);
            }
            #pragma unroll
            for (int mt = 0; mt < 4; ++mt) {
                uint32_t aoff = (uint32_t)(wm * 64 + mt * 16 + (lane & 15)) * 144
                              + (uint32_t)(kc * 16 + ((lane >> 4) & 1) * 8) * 2;
                uint32_t a[4];
                ldsm_x4(a, pA + aoff);
                mma_f16(acc[mt][0], a, &b[0][0]);
                mma_f16(acc[mt][1], a, &b[0][2]);
                mma_f16(acc[mt][2], a, &b[1][0]);
                mma_f16(acc[mt][3], a, &b[1][2]);
            }
        }

        if (t + 2 < nstage) issue(t + 2, (t + 2) % 3);
        CP_COMMIT();
    }

    // epilogue
    const int g   = lane >> 2;
    const int tig = lane & 3;
    const float scale = (MODE == 1 && (bn >> 10) == 0) ? CSC : 1.0f;
    #pragma unroll
    for (int ntl = 0; ntl < 4; ++ntl) {
        int colg = bn + wn * 32 + ntl * 8 + tig * 2;
        float b0 = __ldg(bias + colg);
        float b1 = __ldg(bias + colg + 1);
        #pragma unroll
        for (int mt = 0; mt < 4; ++mt) {
            int row = bm + wm * 64 + mt * 16 + g;
            float v0 = acc[mt][ntl][0] + b0;
            float v1 = acc[mt][ntl][1] + b1;
            float v2 = acc[mt][ntl][2] + b0;
            float v3 = acc[mt][ntl][3] + b1;
            if (MODE == 0) {
                float2 o0, o1;
                o0.x = v0; o0.y = v1;
                o1.x = v2; o1.y = v3;
                *(float2*)&C[(size_t)row * N + colg]       = o0;
                *(float2*)&C[(size_t)(row + 8) * N + colg] = o1;
            } else {
                __half2 h0 = __floats2half2_rn(v0 * scale, v1 * scale);
                __half2 h1 = __floats2half2_rn(v2 * scale, v3 * scale);
                *(uint32_t*)(H + (size_t)row * N + colg)       = *(uint32_t*)&h0;
                *(uint32_t*)(H + (size_t)(row + 8) * N + colg) = *(uint32_t*)&h1;
            }
        }
    }
}

// ---------------------------------------------------------------------------
// Tensor-core flash attention (causal, log2-domain softmax), all-f16 operands.
// Block = (128 queries, head, batch), 8 warps x 16 query rows.
// KV tiles of 128 keys, cp.async double-buffered.
// Reverse-qt launch order: longest CTAs first (causal load imbalance).
// Smem: Q 18432 | 2 x [K 18432 | V 18432] = 92160 bytes.
// ---------------------------------------------------------------------------
#define FL_STAGE 36864
#define FL_SMEM  (18432 + 2 * FL_STAGE)

__global__ __launch_bounds__(256, 1) void flash_mma(
    const __half* __restrict__ qkv, __half* __restrict__ Og)
{
    extern __shared__ __align__(16) char sm[];
    const uint32_t smb = smem_to_u32(sm);
    const uint32_t sQ  = smb;
    const uint32_t sKV = smb + 18432;

    const int tid  = threadIdx.x;
    const int lane = tid & 31;
    const int w    = tid >> 5;
    const int qt   = gridDim.x - 1 - blockIdx.x;   // longest first
    const int h    = blockIdx.y;
    const int b    = blockIdx.z;
    const int q0   = qt * 128;
    const size_t rowbase = (size_t)b * SS;
    const int colb = h * HD;

    auto issue_kv = [&](int kt, int s) {
        const uint32_t dst = sKV + s * FL_STAGE;
        const size_t krow0 = rowbase + (size_t)kt * 128;
        #pragma unroll
        for (int i = 0; i < 4; ++i) {
            int c = (i << 8) + tid;
            int r = c >> 3, ch = c & 7;
            size_t go = (krow0 + r) * (3 * NX) + colb + ch * 8;
            uint32_t so = (uint32_t)(r * 144 + ch * 16);
            CP_ASYNC16(dst + so,         (const char*)(qkv + NX + go));
            CP_ASYNC16(dst + 18432 + so, (const char*)(qkv + 2 * NX + go));
        }
    };

    issue_kv(0, 0);
    CP_COMMIT();

    // load Q tile into smem (f16, single plane)
    {
        int r  = tid >> 1;
        int d0 = (tid & 1) * 32;
        const __half* gq = qkv + (rowbase + q0 + r) * (3 * NX) + colb + d0;
        uint32_t so = (uint32_t)(r * 144 + d0 * 2);
        #pragma unroll
        for (int i = 0; i < 4; ++i)
            *(uint4*)(sm + so + i * 16) = *(const uint4*)(gq + i * 8);
    }

    float O[8][4];
    #pragma unroll
    for (int i = 0; i < 8; ++i)
        #pragma unroll
        for (int j = 0; j < 4; ++j) O[i][j] = 0.0f;
    float mprev_g = -1e30f, mprev_h = -1e30f;
    float lsum_g = 0.0f, lsum_h = 0.0f;

    const uint32_t ones[2] = {0x3C003C00u, 0x3C003C00u};

    for (int kt = 0; kt <= qt; ++kt) {
        if (kt < qt) {
            issue_kv(kt + 1, (kt + 1) & 1);
            CP_COMMIT();
            asm volatile("cp.async.wait_group 1;" ::: "memory");
        } else {
            asm volatile("cp.async.wait_group 0;" ::: "memory");
        }
        __syncthreads();

        const bool diag = (kt == qt);
        const int s = kt & 1;
        const uint32_t bK = sKV + s * FL_STAGE;
        const uint32_t bV = bK + 18432;
        const int nt_max = diag ? 2 * w + 2 : 16;
        const int kc_max = diag ? w + 1 : 8;

        // ---- S = Q K^T (single-term f16) ----
        float sc[16][4];
        #pragma unroll
        for (int i = 0; i < 16; ++i)
            #pragma unroll
            for (int j = 0; j < 4; ++j) sc[i][j] = 0.0f;

        #pragma unroll
        for (int kc = 0; kc < 4; ++kc) {
            uint32_t aoff = (uint32_t)(w * 16 + (lane & 15)) * 144
                          + (uint32_t)(kc * 16 + ((lane >> 4) & 1) * 8) * 2;
            uint32_t a[4];
            ldsm_x4(a, sQ + aoff);
            #pragma unroll
            for (int nt0 = 0; nt0 < 16; nt0 += 2) {
                if (nt0 < nt_max) {
                    uint32_t boff = (uint32_t)(nt0 * 8 + (lane & 7)
                                  + ((lane >> 4) & 1) * 8) * 144
                                  + (uint32_t)(kc * 16 + ((lane >> 3) & 1) * 8) * 2;
                    uint32_t bb[4];
                    ldsm_x4(bb, bK + boff);
                    mma_f16(sc[nt0],     a, &bb[0]);
                    mma_f16(sc[nt0 + 1], a, &bb[2]);
                }
            }
        }

        // ---- causal mask (diag tile) ----
        if (diag) {
            int rg = q0 + w * 16 + (lane >> 2);
            #pragma unroll
            for (int nt = 0; nt < 16; ++nt) {
                if (nt < nt_max) {
                    int cg = q0 + nt * 8 + (lane & 3) * 2;
                    if (cg     > rg)     sc[nt][0] = -1e30f;
                    if (cg + 1 > rg)     sc[nt][1] = -1e30f;
                    if (cg     > rg + 8) sc[nt][2] = -1e30f;
                    if (cg + 1 > rg + 8) sc[nt][3] = -1e30f;
                }
            }
        }

        // ---- online softmax (log2 domain) ----
        float mg = -1e30f, mh = -1e30f;
        #pragma unroll
        for (int nt = 0; nt < 16; ++nt) {
            if (nt < nt_max) {
                mg = fmaxf(mg, fmaxf(sc[nt][0], sc[nt][1]));
                mh = fmaxf(mh, fmaxf(sc[nt][2], sc[nt][3]));
            }
        }
        mg = fmaxf(mg, __shfl_xor_sync(0xffffffffu, mg, 1));
        mg = fmaxf(mg, __shfl_xor_sync(0xffffffffu, mg, 2));
        mh = fmaxf(mh, __shfl_xor_sync(0xffffffffu, mh, 1));
        mh = fmaxf(mh, __shfl_xor_sync(0xffffffffu, mh, 2));
        float mng = fmaxf(mprev_g, mg);
        float mnh = fmaxf(mprev_h, mh);
        float ag  = ex2f(mprev_g - mng);
        float ah2 = ex2f(mprev_h - mnh);
        mprev_g = mng; mprev_h = mnh;
        lsum_g *= ag; lsum_h *= ah2;
        #pragma unroll
        for (int dt = 0; dt < 8; ++dt) {
            O[dt][0] *= ag;  O[dt][1] *= ag;
            O[dt][2] *= ah2; O[dt][3] *= ah2;
        }

        // ---- P = 2^(S - m) packed half2 (A-fragment format) ----
        uint32_t p[16][2];
        #pragma unroll
        for (int nt = 0; nt < 16; ++nt) {
            if (nt < nt_max) {
                p[nt][0] = ex2_pack(sc[nt][1] - mng, sc[nt][0] - mng);
                p[nt][1] = ex2_pack(sc[nt][3] - mnh, sc[nt][2] - mnh);
            }
        }

        // ---- O += P V ; lsum += P @ ones ----
        float ssum[4] = {0.0f, 0.0f, 0.0f, 0.0f};
        #pragma unroll
        for (int kc2 = 0; kc2 < 8; ++kc2) {
            if (kc2 < kc_max) {
                uint32_t a[4] = { p[2 * kc2][0], p[2 * kc2][1],
                                  p[2 * kc2 + 1][0], p[2 * kc2 + 1][1] };
                mma_f16(ssum, a, ones);
                #pragma unroll
                for (int dt0 = 0; dt0 < 8; dt0 += 2) {
                    uint32_t voff = (uint32_t)(kc2 * 16 + (lane & 7)
                                  + ((lane >> 3) & 1) * 8) * 144
                                  + (uint32_t)(dt0 * 8 + ((lane >> 4) & 1) * 8) * 2;
                    uint32_t v4[4];
                    ldsm_x4_t(v4, bV + voff);
                    mma_f16(O[dt0],     a, &v4[0]);
                    mma_f16(O[dt0 + 1], a, &v4[2]);
                }
            }
        }
        lsum_g += ssum[0];
        lsum_h += ssum[2];

        __syncthreads();
    }

    // ---- epilogue: normalize, f16 store (merged heads) ----
    float ig = 1.0f / lsum_g;
    float ih = 1.0f / lsum_h;
    int r0 = q0 + w * 16 + (lane >> 2);
    size_t base0 = (rowbase + r0) * NX + colb + (lane & 3) * 2;
    size_t base1 = base0 + (size_t)8 * NX;
    #pragma unroll
    for (int dt = 0; dt < 8; ++dt) {
        __half2 o0 = __floats2half2_rn(O[dt][0] * ig, O[dt][1] * ig);
        __half2 o1 = __floats2half2_rn(O[dt][2] * ih, O[dt][3] * ih);
        *(uint32_t*)(Og + base0 + dt * 8) = *(uint32_t*)&o0;
        *(uint32_t*)(Og + base1 + dt * 8) = *(uint32_t*)&o1;
    }
}

// ---------------------------------------------------------------------------
extern "C" void kernel_launch(void* const* d_in, const int* in_sizes, int n_in,
                              void* d_out, int out_size)
{
    const float* x      = (const float*)d_in[0];
    const float* w_attn = (const float*)d_in[1];
    const float* b_attn = (const float*)d_in[2];
    const float* w_proj = (const float*)d_in[3];
    const float* b_proj = (const float*)d_in[4];
    float* out = (float*)d_out;

    __half *xh, *wat, *wpt, *qkvh, *oh;
    cudaGetSymbolAddress((void**)&xh,   g_xh);
    cudaGetSymbolAddress((void**)&wat,  g_wat);
    cudaGetSymbolAddress((void**)&wpt,  g_wpt);
    cudaGetSymbolAddress((void**)&qkvh, g_qkvh);
    cudaGetSymbolAddress((void**)&oh,   g_oh);

    // prepass
    {
        int n4 = BB * SS * NX / 4;
        to_f16<<<(n4 + 255) / 256, 256>>>((const float4*)x, xh, n4);
        transpose_f16<<<dim3(3 * NX / 32, NX / 32), dim3(32, 8)>>>(
            w_attn, wat, NX, 3 * NX);
        transpose_f16<<<dim3(NX / 32, NX / 32), dim3(32, 8)>>>(
            w_proj, wpt, NX, NX);
    }

    cudaFuncSetAttribute(gemm_f16<0>, cudaFuncAttributeMaxDynamicSharedMemorySize,
                         GEMM_SMEM);
    cudaFuncSetAttribute(gemm_f16<1>, cudaFuncAttributeMaxDynamicSharedMemorySize,
                         GEMM_SMEM);
    cudaFuncSetAttribute(flash_mma, cudaFuncAttributeMaxDynamicSharedMemorySize,
                         FL_SMEM);

    // 1) QKV projection -> f16 qkv (Q pre-scaled by CSC)
    {
        dim3 grid(3 * NX / 128, BB * SS / 128);   // 24 x 64
        gemm_f16<1><<<grid, 256, GEMM_SMEM>>>(
            xh, wat, b_attn, nullptr, qkvh, 3 * NX, NX);
    }

    // 2) flash attention -> f16 merged heads
    {
        dim3 grid(SS / 128, NH, BB);
        flash_mma<<<grid, 256, FL_SMEM>>>(qkvh, oh);
    }

    // 3) out = O @ w_proj + b_proj (fp32 out)
    {
        dim3 grid(NX / 128, BB * SS / 128);       // 8 x 64
        gemm_f16<0><<<grid, 256, GEMM_SMEM>>>(
            oh, wpt, b_proj, out, nullptr, NX, NX);
    }
}

// round 9
// speedup vs baseline: 7.0184x; 1.0476x over previous
#include <cuda_runtime.h>
#include <cuda_bf16.h>
#include <cuda_fp16.h>
#include <cstdint>

// Problem constants
#define BB 8
#define SS 1024
#define NX 1024
#define NH 16
#define HD 64

// log2(e) / sqrt(64) folded into Q
#define CSC 0.18033688011112042592f

// ---------------------------------------------------------------------------
// Scratch (device globals; allocation-free rule)
// ---------------------------------------------------------------------------
__device__ __half g_xh[(size_t)BB * SS * NX];           // x in f16
__device__ __half g_wat[(size_t)3 * NX * NX];           // w_attn^T [3NX][NX] f16
__device__ __half g_wpt[(size_t)NX * NX];               // w_proj^T [NX][NX] f16
__device__ __half g_qkvh[(size_t)BB * SS * 3 * NX];     // QKV (Q pre-scaled) f16
__device__ __half g_oh[(size_t)BB * SS * NX];           // attention out f16

__device__ __forceinline__ uint32_t smem_to_u32(const void* p) {
    uint32_t a;
    asm("{ .reg .u64 t; cvta.to.shared.u64 t, %1; cvt.u32.u64 %0, t; }"
        : "=r"(a) : "l"(p));
    return a;
}

// ---------------------------------------------------------------------------
// MMA / ldmatrix / misc helpers
// ---------------------------------------------------------------------------
__device__ __forceinline__ void mma_f16(float* d, const uint32_t* a,
                                        const uint32_t* b) {
    asm volatile(
        "mma.sync.aligned.m16n8k16.row.col.f32.f16.f16.f32 "
        "{%0,%1,%2,%3}, {%4,%5,%6,%7}, {%8,%9}, {%0,%1,%2,%3};"
        : "+f"(d[0]), "+f"(d[1]), "+f"(d[2]), "+f"(d[3])
        : "r"(a[0]), "r"(a[1]), "r"(a[2]), "r"(a[3]), "r"(b[0]), "r"(b[1]));
}

__device__ __forceinline__ void ldsm_x4(uint32_t* r, uint32_t addr) {
    asm volatile("ldmatrix.sync.aligned.m8n8.x4.shared.b16 {%0,%1,%2,%3}, [%4];"
                 : "=r"(r[0]), "=r"(r[1]), "=r"(r[2]), "=r"(r[3]) : "r"(addr));
}

__device__ __forceinline__ void ldsm_x4_t(uint32_t* r, uint32_t addr) {
    asm volatile("ldmatrix.sync.aligned.m8n8.x4.trans.shared.b16 {%0,%1,%2,%3}, [%4];"
                 : "=r"(r[0]), "=r"(r[1]), "=r"(r[2]), "=r"(r[3]) : "r"(addr));
}

__device__ __forceinline__ float ex2f(float x) {
    float r;
    asm("ex2.approx.ftz.f32 %0, %1;" : "=f"(r) : "f"(x));
    return r;
}

__device__ __forceinline__ uint32_t ex2_pack(float hi, float lo) {
    uint32_t t, r;
    asm("cvt.rn.f16x2.f32 %0, %1, %2;" : "=r"(t) : "f"(hi), "f"(lo));
    asm("ex2.approx.f16x2 %0, %1;" : "=r"(r) : "r"(t));
    return r;
}

#define CP_ASYNC16(dst, src) \
    asm volatile("cp.async.cg.shared.global [%0], [%1], 16;" \
                 :: "r"(dst), "l"(src) : "memory")
#define CP_COMMIT() asm volatile("cp.async.commit_group;" ::: "memory")

// ---------------------------------------------------------------------------
// Prepass kernels
// ---------------------------------------------------------------------------
__global__ void to_f16(const float4* __restrict__ in, __half* __restrict__ out,
                       int n4)
{
    int i = blockIdx.x * blockDim.x + threadIdx.x;
    if (i >= n4) return;
    float4 v = in[i];
    __half2 a = __floats2half2_rn(v.x, v.y);
    __half2 b = __floats2half2_rn(v.z, v.w);
    uint2 w;
    w.x = *(uint32_t*)&a;
    w.y = *(uint32_t*)&b;
    *(uint2*)(out + (size_t)i * 4) = w;
}

// transpose K x C fp32 -> [C][K] f16
__global__ void transpose_f16(const float* __restrict__ in,
                              __half* __restrict__ outT, int Kdim, int Cdim)
{
    __shared__ float tile[32][33];
    int bx = blockIdx.x * 32;
    int by = blockIdx.y * 32;
    int x = threadIdx.x, y = threadIdx.y;   // 32 x 8
    #pragma unroll
    for (int j = 0; j < 4; ++j)
        tile[y + j * 8][x] = in[(size_t)(by + y + j * 8) * Cdim + bx + x];
    __syncthreads();
    #pragma unroll
    for (int j = 0; j < 4; ++j) {
        float v = tile[x][y + j * 8];
        outT[(size_t)(bx + y + j * 8) * Kdim + by + x] = __float2half(v);
    }
}

// ---------------------------------------------------------------------------
// Single-term f16 GEMM: C(MxN) = A(MxK) @ BT(NxK)^T + bias.
// 128x128 block tile, BK=64, 3-stage cp.async pipeline, 8 warps (2x4),
// warp tile 64x32, 2 CTAs per SM (cross-CTA latency hiding).
// Per stage: all 8 B-ldsm hoisted up front (independent, pipelined), then
// kc loop body is A-ldsm -> 4 MMA only.
// MODE 0: fp32 out + bias.   MODE 1: f16 out + bias, xCSC on Q segment.
// ---------------------------------------------------------------------------
#define GSTAGES   3
#define GPLANE_B  18432                  // 128 * 144
#define GSTAGE_B  36864                  // A + B planes
#define GEMM_SMEM (GSTAGES * GSTAGE_B)   // 110592 -> 2 CTAs/SM

template<int MODE>
__global__ __launch_bounds__(256, 2) void gemm_f16(
    const __half* __restrict__ A, const __half* __restrict__ BT,
    const float* __restrict__ bias, float* __restrict__ C,
    __half* __restrict__ H, int N, int K)
{
    extern __shared__ __align__(16) char sm[];
    const uint32_t smb = smem_to_u32(sm);

    const int tid  = threadIdx.x;
    const int lane = tid & 31;
    const int warp = tid >> 5;
    const int wm   = warp >> 2;        // 0..1
    const int wn   = warp & 3;         // 0..3
    const int bm   = blockIdx.y * 128;
    const int bn   = blockIdx.x * 128;

    auto issue = [&](int t, int s) {
        const uint32_t dst = smb + s * GSTAGE_B;
        const size_t k0 = (size_t)t * 64;
        #pragma unroll
        for (int i = 0; i < 4; ++i) {
            int c = (i << 8) + tid;
            int r = c >> 3, ch = c & 7;
            uint32_t so = (uint32_t)(r * 144 + ch * 16);
            CP_ASYNC16(dst + so,
                       (const char*)(A + (size_t)(bm + r) * K + k0 + ch * 8));
            CP_ASYNC16(dst + GPLANE_B + so,
                       (const char*)(BT + (size_t)(bn + r) * K + k0 + ch * 8));
        }
    };

    float acc[4][4][4];
    #pragma unroll
    for (int i = 0; i < 4; ++i)
        #pragma unroll
        for (int j = 0; j < 4; ++j)
            #pragma unroll
            for (int k = 0; k < 4; ++k) acc[i][j][k] = 0.0f;

    const int nstage = K >> 6;   // 16

    issue(0, 0);
    CP_COMMIT();
    issue(1, 1);
    CP_COMMIT();

    for (int t = 0; t < nstage; ++t) {
        asm volatile("cp.async.wait_group 1;" ::: "memory");
        __syncthreads();

        const int slot = t % 3;
        const uint32_t pA = smb + slot * GSTAGE_B;
        const uint32_t pB = pA + GPLANE_B;

        // hoist all B fragments for this stage (8 independent ldsm)
        uint32_t ball[4][2][4];
        #pragma unroll
        for (int kc = 0; kc < 4; ++kc) {
            #pragma unroll
            for (int pr = 0; pr < 2; ++pr) {
                uint32_t boff = (uint32_t)(wn * 32 + pr * 16
                              + ((lane >> 4) & 1) * 8 + (lane & 7)) * 144
                              + (uint32_t)(kc * 16 + ((lane >> 3) & 1) * 8) * 2;
                ldsm_x4(ball[kc][pr], pB + boff);
            }
        }

        #pragma unroll
        for (int kc = 0; kc < 4; ++kc) {
            #pragma unroll
            for (int mt = 0; mt < 4; ++mt) {
                uint32_t aoff = (uint32_t)(wm * 64 + mt * 16 + (lane & 15)) * 144
                              + (uint32_t)(kc * 16 + ((lane >> 4) & 1) * 8) * 2;
                uint32_t a[4];
                ldsm_x4(a, pA + aoff);
                mma_f16(acc[mt][0], a, &ball[kc][0][0]);
                mma_f16(acc[mt][1], a, &ball[kc][0][2]);
                mma_f16(acc[mt][2], a, &ball[kc][1][0]);
                mma_f16(acc[mt][3], a, &ball[kc][1][2]);
            }
        }

        if (t + 2 < nstage) issue(t + 2, (t + 2) % 3);
        CP_COMMIT();
    }

    // epilogue
    const int g   = lane >> 2;
    const int tig = lane & 3;
    const float scale = (MODE == 1 && (bn >> 10) == 0) ? CSC : 1.0f;
    #pragma unroll
    for (int ntl = 0; ntl < 4; ++ntl) {
        int colg = bn + wn * 32 + ntl * 8 + tig * 2;
        float b0 = __ldg(bias + colg);
        float b1 = __ldg(bias + colg + 1);
        #pragma unroll
        for (int mt = 0; mt < 4; ++mt) {
            int row = bm + wm * 64 + mt * 16 + g;
            float v0 = acc[mt][ntl][0] + b0;
            float v1 = acc[mt][ntl][1] + b1;
            float v2 = acc[mt][ntl][2] + b0;
            float v3 = acc[mt][ntl][3] + b1;
            if (MODE == 0) {
                float2 o0, o1;
                o0.x = v0; o0.y = v1;
                o1.x = v2; o1.y = v3;
                *(float2*)&C[(size_t)row * N + colg]       = o0;
                *(float2*)&C[(size_t)(row + 8) * N + colg] = o1;
            } else {
                __half2 h0 = __floats2half2_rn(v0 * scale, v1 * scale);
                __half2 h1 = __floats2half2_rn(v2 * scale, v3 * scale);
                *(uint32_t*)(H + (size_t)row * N + colg)       = *(uint32_t*)&h0;
                *(uint32_t*)(H + (size_t)(row + 8) * N + colg) = *(uint32_t*)&h1;
            }
        }
    }
}

// ---------------------------------------------------------------------------
// Tensor-core flash attention (causal, log2-domain softmax), all-f16 operands.
// Block = (128 queries, head, batch), 8 warps x 16 query rows.
// KV tiles of 128 keys, cp.async double-buffered. 2 CTAs per SM.
// P = ex2(S - m) is computed inside the PV loop (keeps register peak < 128).
// Reverse-qt launch order: longest CTAs first (causal load imbalance).
// Smem: Q 18432 | 2 x [K 18432 | V 18432] = 92160 bytes.
// ---------------------------------------------------------------------------
#define FL_STAGE 36864
#define FL_SMEM  (18432 + 2 * FL_STAGE)

__global__ __launch_bounds__(256, 2) void flash_mma(
    const __half* __restrict__ qkv, __half* __restrict__ Og)
{
    extern __shared__ __align__(16) char sm[];
    const uint32_t smb = smem_to_u32(sm);
    const uint32_t sQ  = smb;
    const uint32_t sKV = smb + 18432;

    const int tid  = threadIdx.x;
    const int lane = tid & 31;
    const int w    = tid >> 5;
    const int qt   = gridDim.x - 1 - blockIdx.x;   // longest first
    const int h    = blockIdx.y;
    const int b    = blockIdx.z;
    const int q0   = qt * 128;
    const size_t rowbase = (size_t)b * SS;
    const int colb = h * HD;

    auto issue_kv = [&](int kt, int s) {
        const uint32_t dst = sKV + s * FL_STAGE;
        const size_t krow0 = rowbase + (size_t)kt * 128;
        #pragma unroll
        for (int i = 0; i < 4; ++i) {
            int c = (i << 8) + tid;
            int r = c >> 3, ch = c & 7;
            size_t go = (krow0 + r) * (3 * NX) + colb + ch * 8;
            uint32_t so = (uint32_t)(r * 144 + ch * 16);
            CP_ASYNC16(dst + so,         (const char*)(qkv + NX + go));
            CP_ASYNC16(dst + 18432 + so, (const char*)(qkv + 2 * NX + go));
        }
    };

    issue_kv(0, 0);
    CP_COMMIT();

    // load Q tile into smem (f16, single plane)
    {
        int r  = tid >> 1;
        int d0 = (tid & 1) * 32;
        const __half* gq = qkv + (rowbase + q0 + r) * (3 * NX) + colb + d0;
        uint32_t so = (uint32_t)(r * 144 + d0 * 2);
        #pragma unroll
        for (int i = 0; i < 4; ++i)
            *(uint4*)(sm + so + i * 16) = *(const uint4*)(gq + i * 8);
    }

    float O[8][4];
    #pragma unroll
    for (int i = 0; i < 8; ++i)
        #pragma unroll
        for (int j = 0; j < 4; ++j) O[i][j] = 0.0f;
    float mprev_g = -1e30f, mprev_h = -1e30f;
    float lsum_g = 0.0f, lsum_h = 0.0f;

    const uint32_t ones[2] = {0x3C003C00u, 0x3C003C00u};

    for (int kt = 0; kt <= qt; ++kt) {
        if (kt < qt) {
            issue_kv(kt + 1, (kt + 1) & 1);
            CP_COMMIT();
            asm volatile("cp.async.wait_group 1;" ::: "memory");
        } else {
            asm volatile("cp.async.wait_group 0;" ::: "memory");
        }
        __syncthreads();

        const bool diag = (kt == qt);
        const int s = kt & 1;
        const uint32_t bK = sKV + s * FL_STAGE;
        const uint32_t bV = bK + 18432;
        const int nt_max = diag ? 2 * w + 2 : 16;
        const int kc_max = diag ? w + 1 : 8;

        // ---- S = Q K^T (single-term f16) ----
        float sc[16][4];
        #pragma unroll
        for (int i = 0; i < 16; ++i)
            #pragma unroll
            for (int j = 0; j < 4; ++j) sc[i][j] = 0.0f;

        #pragma unroll
        for (int kc = 0; kc < 4; ++kc) {
            uint32_t aoff = (uint32_t)(w * 16 + (lane & 15)) * 144
                          + (uint32_t)(kc * 16 + ((lane >> 4) & 1) * 8) * 2;
            uint32_t a[4];
            ldsm_x4(a, sQ + aoff);
            #pragma unroll
            for (int nt0 = 0; nt0 < 16; nt0 += 2) {
                if (nt0 < nt_max) {
                    uint32_t boff = (uint32_t)(nt0 * 8 + (lane & 7)
                                  + ((lane >> 4) & 1) * 8) * 144
                                  + (uint32_t)(kc * 16 + ((lane >> 3) & 1) * 8) * 2;
                    uint32_t bb[4];
                    ldsm_x4(bb, bK + boff);
                    mma_f16(sc[nt0],     a, &bb[0]);
                    mma_f16(sc[nt0 + 1], a, &bb[2]);
                }
            }
        }

        // ---- causal mask (diag tile) ----
        if (diag) {
            int rg = q0 + w * 16 + (lane >> 2);
            #pragma unroll
            for (int nt = 0; nt < 16; ++nt) {
                if (nt < nt_max) {
                    int cg = q0 + nt * 8 + (lane & 3) * 2;
                    if (cg     > rg)     sc[nt][0] = -1e30f;
                    if (cg + 1 > rg)     sc[nt][1] = -1e30f;
                    if (cg     > rg + 8) sc[nt][2] = -1e30f;
                    if (cg + 1 > rg + 8) sc[nt][3] = -1e30f;
                }
            }
        }

        // ---- online softmax (log2 domain) ----
        float mg = -1e30f, mh = -1e30f;
        #pragma unroll
        for (int nt = 0; nt < 16; ++nt) {
            if (nt < nt_max) {
                mg = fmaxf(mg, fmaxf(sc[nt][0], sc[nt][1]));
                mh = fmaxf(mh, fmaxf(sc[nt][2], sc[nt][3]));
            }
        }
        mg = fmaxf(mg, __shfl_xor_sync(0xffffffffu, mg, 1));
        mg = fmaxf(mg, __shfl_xor_sync(0xffffffffu, mg, 2));
        mh = fmaxf(mh, __shfl_xor_sync(0xffffffffu, mh, 1));
        mh = fmaxf(mh, __shfl_xor_sync(0xffffffffu, mh, 2));
        float mng = fmaxf(mprev_g, mg);
        float mnh = fmaxf(mprev_h, mh);
        float ag  = ex2f(mprev_g - mng);
        float ah2 = ex2f(mprev_h - mnh);
        mprev_g = mng; mprev_h = mnh;
        lsum_g *= ag; lsum_h *= ah2;
        #pragma unroll
        for (int dt = 0; dt < 8; ++dt) {
            O[dt][0] *= ag;  O[dt][1] *= ag;
            O[dt][2] *= ah2; O[dt][3] *= ah2;
        }

        // ---- O += P V ; lsum += P @ ones  (P computed in-loop via ex2) ----
        float ssum[4] = {0.0f, 0.0f, 0.0f, 0.0f};
        #pragma unroll
        for (int kc2 = 0; kc2 < 8; ++kc2) {
            if (kc2 < kc_max) {
                uint32_t a[4];
                a[0] = ex2_pack(sc[2 * kc2][1] - mng, sc[2 * kc2][0] - mng);
                a[1] = ex2_pack(sc[2 * kc2][3] - mnh, sc[2 * kc2][2] - mnh);
                a[2] = ex2_pack(sc[2 * kc2 + 1][1] - mng, sc[2 * kc2 + 1][0] - mng);
                a[3] = ex2_pack(sc[2 * kc2 + 1][3] - mnh, sc[2 * kc2 + 1][2] - mnh);
                mma_f16(ssum, a, ones);
                #pragma unroll
                for (int dt0 = 0; dt0 < 8; dt0 += 2) {
                    uint32_t voff = (uint32_t)(kc2 * 16 + (lane & 7)
                                  + ((lane >> 3) & 1) * 8) * 144
                                  + (uint32_t)(dt0 * 8 + ((lane >> 4) & 1) * 8) * 2;
                    uint32_t v4[4];
                    ldsm_x4_t(v4, bV + voff);
                    mma_f16(O[dt0],     a, &v4[0]);
                    mma_f16(O[dt0 + 1], a, &v4[2]);
                }
            }
        }
        lsum_g += ssum[0];
        lsum_h += ssum[2];

        __syncthreads();
    }

    // ---- epilogue: normalize, f16 store (merged heads) ----
    float ig = 1.0f / lsum_g;
    float ih = 1.0f / lsum_h;
    int r0 = q0 + w * 16 + (lane >> 2);
    size_t base0 = (rowbase + r0) * NX + colb + (lane & 3) * 2;
    size_t base1 = base0 + (size_t)8 * NX;
    #pragma unroll
    for (int dt = 0; dt < 8; ++dt) {
        __half2 o0 = __floats2half2_rn(O[dt][0] * ig, O[dt][1] * ig);
        __half2 o1 = __floats2half2_rn(O[dt][2] * ih, O[dt][3] * ih);
        *(uint32_t*)(Og + base0 + dt * 8) = *(uint32_t*)&o0;
        *(uint32_t*)(Og + base1 + dt * 8) = *(uint32_t*)&o1;
    }
}

// ---------------------------------------------------------------------------
extern "C" void kernel_launch(void* const* d_in, const int* in_sizes, int n_in,
                              void* d_out, int out_size)
{
    const float* x      = (const float*)d_in[0];
    const float* w_attn = (const float*)d_in[1];
    const float* b_attn = (const float*)d_in[2];
    const float* w_proj = (const float*)d_in[3];
    const float* b_proj = (const float*)d_in[4];
    float* out = (float*)d_out;

    __half *xh, *wat, *wpt, *qkvh, *oh;
    cudaGetSymbolAddress((void**)&xh,   g_xh);
    cudaGetSymbolAddress((void**)&wat,  g_wat);
    cudaGetSymbolAddress((void**)&wpt,  g_wpt);
    cudaGetSymbolAddress((void**)&qkvh, g_qkvh);
    cudaGetSymbolAddress((void**)&oh,   g_oh);

    // prepass
    {
        int n4 = BB * SS * NX / 4;
        to_f16<<<(n4 + 255) / 256, 256>>>((const float4*)x, xh, n4);
        transpose_f16<<<dim3(3 * NX / 32, NX / 32), dim3(32, 8)>>>(
            w_attn, wat, NX, 3 * NX);
        transpose_f16<<<dim3(NX / 32, NX / 32), dim3(32, 8)>>>(
            w_proj, wpt, NX, NX);
    }

    cudaFuncSetAttribute(gemm_f16<0>, cudaFuncAttributeMaxDynamicSharedMemorySize,
                         GEMM_SMEM);
    cudaFuncSetAttribute(gemm_f16<1>, cudaFuncAttributeMaxDynamicSharedMemorySize,
                         GEMM_SMEM);
    cudaFuncSetAttribute(flash_mma, cudaFuncAttributeMaxDynamicSharedMemorySize,
                         FL_SMEM);

    // 1) QKV projection -> f16 qkv (Q pre-scaled by CSC)
    {
        dim3 grid(3 * NX / 128, BB * SS / 128);   // 24 x 64
        gemm_f16<1><<<grid, 256, GEMM_SMEM>>>(
            xh, wat, b_attn, nullptr, qkvh, 3 * NX, NX);
    }

    // 2) flash attention -> f16 merged heads
    {
        dim3 grid(SS / 128, NH, BB);
        flash_mma<<<grid, 256, FL_SMEM>>>(qkvh, oh);
    }

    // 3) out = O @ w_proj + b_proj (fp32 out)
    {
        dim3 grid(NX / 128, BB * SS / 128);       // 8 x 64
        gemm_f16<0><<<grid, 256, GEMM_SMEM>>>(
            oh, wpt, b_proj, out, nullptr, NX, NX);
    }
}